// round 10
// baseline (speedup 1.0000x reference)
#include <cuda_runtime.h>
#include <math.h>

#define NB 16
#define NPT 4096
#define MTOT (NB*NPT)   // 65536 points

__device__ __forceinline__ float gelu_f(float x) {
    return 0.5f * x * (1.0f + tanhf(0.7978845608028654f * (x + 0.044715f * x * x * x)));
}

// ---------------- scratch buffers (device globals; no allocs allowed) ----------------
__device__ float g_c1[NB*16*112*112];      // plane conv1 out
__device__ float g_c2[NB*32*56*56];        // plane conv2 out
__device__ float g_fmap[NB*4*56*56];       // plane conv3 out (fmap)
__device__ float g_ga[NB*4*112*112];       // global enc stages
__device__ float g_gb[NB*8*56*56];
__device__ float g_gcs[NB*16*28*28];
__device__ float g_gd[NB*32*14*14];
__device__ float g_ge[NB*64*7*7];
__device__ float g_gvec[NB*64];            // pooled global code
__device__ float g_gcon[NB*512];           // gc @ W_gc^T per batch
__device__ float g_Wcat[512*512];          // [Wcomb | W_patch]
__device__ float g_biasC[512];             // hb1 + W_pf @ lb2
__device__ float g_embed[MTOT*48];
__device__ float g_feat[(size_t)MTOT*512]; // [h2 | patches]
__device__ float g_hidden[(size_t)MTOT*512];

// ---------------- generic 3x3 conv, pad 1, stride s, gelu ----------------
__global__ void conv3x3_gelu(const float* __restrict__ in, const float* __restrict__ w,
                             const float* __restrict__ bias, float* __restrict__ out,
                             int B, int Cin, int Hin, int Win, int Cout, int Hout, int Wout,
                             int stride) {
    int idx = blockIdx.x * blockDim.x + threadIdx.x;
    int total = B * Cout * Hout * Wout;
    if (idx >= total) return;
    int ox = idx % Wout; int t = idx / Wout;
    int oy = t % Hout;   t /= Hout;
    int co = t % Cout;   int b = t / Cout;
    float acc = bias[co];
    const float* wp = w + co * Cin * 9;
    const float* ip = in + (size_t)b * Cin * Hin * Win;
    int iy0 = oy * stride - 1, ix0 = ox * stride - 1;
    for (int ci = 0; ci < Cin; ci++) {
        const float* ipc = ip + (size_t)ci * Hin * Win;
        const float* wpc = wp + ci * 9;
        #pragma unroll
        for (int ky = 0; ky < 3; ky++) {
            int iy = iy0 + ky;
            if (iy < 0 || iy >= Hin) continue;
            #pragma unroll
            for (int kx = 0; kx < 3; kx++) {
                int ix = ix0 + kx;
                if (ix < 0 || ix >= Win) continue;
                acc += ipc[iy * Win + ix] * wpc[ky * 3 + kx];
            }
        }
    }
    out[idx] = gelu_f(acc);
}

// ---------------- global pooling: mean over 7x7 ----------------
__global__ void gpool_kernel() {
    int idx = blockIdx.x * blockDim.x + threadIdx.x;  // 16*64
    if (idx >= NB * 64) return;
    const float* p = g_ge + idx * 49;
    float s = 0.f;
    #pragma unroll
    for (int i = 0; i < 49; i++) s += p[i];
    g_gvec[idx] = s * (1.0f / 49.0f);
}

// ---------------- per-batch gc contribution: gcon[b,j] = sum_c gc[b,c]*hw1[j,512+c] ----
__global__ void gcon_kernel(const float* __restrict__ hw1) {
    int idx = blockIdx.x * blockDim.x + threadIdx.x;  // 16*512
    if (idx >= NB * 512) return;
    int b = idx >> 9, j = idx & 511;
    float acc = 0.f;
    const float* gv = g_gvec + b * 64;
    const float* hp = hw1 + j * 576 + 512;
    #pragma unroll
    for (int c = 0; c < 64; c++) acc += gv[c] * hp[c];
    g_gcon[idx] = acc;
}

// ---------------- head weight prep: Wcat = [hw1[:,0:256]@lw2 | hw1[:,256:512]] --------
__global__ void prep_head(const float* __restrict__ hw1, const float* __restrict__ hb1,
                          const float* __restrict__ lw2, const float* __restrict__ lb2) {
    int j = blockIdx.x;       // 512
    int t = threadIdx.x;      // 256
    const float* hrow = hw1 + j * 576;
    float acc = 0.f;
    for (int c = 0; c < 256; c++)
        acc += hrow[c] * lw2[c * 256 + t];
    g_Wcat[j * 512 + t] = acc;
    g_Wcat[j * 512 + 256 + t] = hrow[256 + t];
    __shared__ float s[256];
    s[t] = hrow[t] * lb2[t];
    __syncthreads();
    for (int o = 128; o > 0; o >>= 1) {
        if (t < o) s[t] += s[t + o];
        __syncthreads();
    }
    if (t == 0) g_biasC[j] = hb1[j] + s[0];
}

// ---------------- positional embedding ----------------
__global__ void embed_kernel(const float* __restrict__ points) {
    int idx = blockIdx.x * blockDim.x + threadIdx.x;  // MTOT*12
    if (idx >= MTOT * 12) return;
    int m = idx / 12, i = idx % 12;
    float f = (float)(1 << i);
    float px = points[m * 2 + 0], py = points[m * 2 + 1];
    float sx, cx, sy, cy;
    sincosf(f * px, &sx, &cx);
    sincosf(f * py, &sy, &cy);
    float* e = g_embed + m * 48 + 4 * i;
    e[0] = sx; e[1] = sy; e[2] = cx; e[3] = cy;
}

// ---------------- bilinear patch gather into g_feat cols [256,512) -------------------
__global__ void patch_kernel(const float* __restrict__ points) {
    int idx = blockIdx.x * blockDim.x + threadIdx.x;  // MTOT*64
    if (idx >= MTOT * 64) return;
    int pp = idx & 63;
    int m = idx >> 6;
    int i = pp >> 3, j = pp & 7;          // i -> x offset, j -> y offset
    int b = m >> 12;
    float px = points[m * 2 + 0], py = points[m * 2 + 1];
    const float step = 2.0f / 55.0f;
    float gx = (px * 2.0f - 1.0f) + ((float)i - 3.5f) * step;
    float gy = (py * 2.0f - 1.0f) + ((float)j - 3.5f) * step;
    float ix = (gx + 1.0f) * 0.5f * 55.0f;
    float iy = (gy + 1.0f) * 0.5f * 55.0f;
    float x0f = floorf(ix), y0f = floorf(iy);
    int x0 = (int)x0f, y0 = (int)y0f;
    int x1 = x0 + 1, y1 = y0 + 1;
    float wx1 = ix - x0f, wx0 = 1.0f - wx1;
    float wy1 = iy - y0f, wy0 = 1.0f - wy1;
    bool vx0 = (x0 >= 0) & (x0 < 56), vx1 = (x1 >= 0) & (x1 < 56);
    bool vy0 = (y0 >= 0) & (y0 < 56), vy1 = (y1 >= 0) & (y1 < 56);
    int cx0 = min(max(x0, 0), 55), cx1 = min(max(x1, 0), 55);
    int cy0 = min(max(y0, 0), 55), cy1 = min(max(y1, 0), 55);
    float w00 = wx0 * wy0 * ((vx0 && vy0) ? 1.f : 0.f);
    float w10 = wx1 * wy0 * ((vx1 && vy0) ? 1.f : 0.f);
    float w01 = wx0 * wy1 * ((vx0 && vy1) ? 1.f : 0.f);
    float w11 = wx1 * wy1 * ((vx1 && vy1) ? 1.f : 0.f);
    int i00 = cy0 * 56 + cx0, i10 = cy0 * 56 + cx1;
    int i01 = cy1 * 56 + cx0, i11 = cy1 * 56 + cx1;
    const float* fm = g_fmap + (size_t)b * 4 * 3136;
    float* fo = g_feat + (size_t)m * 512 + 256 + pp;
    #pragma unroll
    for (int c = 0; c < 4; c++) {
        const float* base = fm + c * 3136;
        float v = w00 * base[i00] + w10 * base[i10] + w01 * base[i01] + w11 * base[i11];
        fo[c * 64] = v;
    }
}

// ---------------- tiled SGEMM: C[M,N] = gelu(A[M,K] @ W[N,K]^T + bias (+ gcon)) ------
// BM=BN=128, BK=8, 256 threads, 8x8 per thread
__global__ __launch_bounds__(256) void sgemm128(
    const float* __restrict__ A, int lda,
    const float* __restrict__ W, int K,
    float* __restrict__ C, int ldc,
    const float* __restrict__ bias,
    const float* __restrict__ gcon) {
    __shared__ float As[8][128];
    __shared__ float Bs[8][128];
    int tid = threadIdx.x;
    int blockM = blockIdx.y * 128;
    int blockN = blockIdx.x * 128;
    int ty = tid >> 4, tx = tid & 15;
    int arow = tid >> 1;
    int acol = (tid & 1) * 4;
    const float* Aptr = A + (size_t)(blockM + arow) * lda + acol;
    const float* Wptr = W + (size_t)(blockN + arow) * K + acol;

    float acc[8][8];
    #pragma unroll
    for (int i = 0; i < 8; i++)
        #pragma unroll
        for (int j = 0; j < 8; j++) acc[i][j] = 0.f;

    for (int k0 = 0; k0 < K; k0 += 8) {
        float4 av = *reinterpret_cast<const float4*>(Aptr + k0);
        float4 wv = *reinterpret_cast<const float4*>(Wptr + k0);
        As[acol + 0][arow] = av.x; As[acol + 1][arow] = av.y;
        As[acol + 2][arow] = av.z; As[acol + 3][arow] = av.w;
        Bs[acol + 0][arow] = wv.x; Bs[acol + 1][arow] = wv.y;
        Bs[acol + 2][arow] = wv.z; Bs[acol + 3][arow] = wv.w;
        __syncthreads();
        #pragma unroll
        for (int k = 0; k < 8; k++) {
            float a[8], bb[8];
            #pragma unroll
            for (int i = 0; i < 8; i++) a[i] = As[k][ty * 8 + i];
            #pragma unroll
            for (int j = 0; j < 8; j++) bb[j] = Bs[k][tx * 8 + j];
            #pragma unroll
            for (int i = 0; i < 8; i++)
                #pragma unroll
                for (int j = 0; j < 8; j++)
                    acc[i][j] += a[i] * bb[j];
        }
        __syncthreads();
    }
    #pragma unroll
    for (int i = 0; i < 8; i++) {
        int row = blockM + ty * 8 + i;
        const float* grow = gcon ? (gcon + (size_t)(row >> 12) * 512) : nullptr;
        float* crow = C + (size_t)row * ldc;
        #pragma unroll
        for (int j = 0; j < 8; j++) {
            int col = blockN + tx * 8 + j;
            float v = acc[i][j] + bias[col];
            if (grow) v += grow[col];
            crow[col] = gelu_f(v);
        }
    }
}

// ---------------- final dot with hw2 ----------------
__global__ void head_reduce(const float* __restrict__ hw2, const float* __restrict__ hb2,
                            float* __restrict__ out) {
    int m = blockIdx.x * 8 + (threadIdx.x >> 5);
    int lane = threadIdx.x & 31;
    const float* h = g_hidden + (size_t)m * 512;
    float s = 0.f;
    #pragma unroll
    for (int j0 = 0; j0 < 512; j0 += 32)
        s += h[j0 + lane] * hw2[j0 + lane];
    #pragma unroll
    for (int o = 16; o > 0; o >>= 1) s += __shfl_xor_sync(0xFFFFFFFFu, s, o);
    if (lane == 0) out[m] = s + hb2[0];
}

// =====================================================================================
extern "C" void kernel_launch(void* const* d_in, const int* in_sizes, int n_in,
                              void* d_out, int out_size) {
    const float* points = (const float*)d_in[0];
    const float* images = (const float*)d_in[1];
    const float* pw1 = (const float*)d_in[2];  const float* pb1 = (const float*)d_in[3];
    const float* pw2 = (const float*)d_in[4];  const float* pb2 = (const float*)d_in[5];
    const float* pw3 = (const float*)d_in[6];  const float* pb3 = (const float*)d_in[7];
    const float* gw1 = (const float*)d_in[8];  const float* gb1 = (const float*)d_in[9];
    const float* gw2 = (const float*)d_in[10]; const float* gb2 = (const float*)d_in[11];
    const float* gw3 = (const float*)d_in[12]; const float* gb3 = (const float*)d_in[13];
    const float* gw4 = (const float*)d_in[14]; const float* gb4 = (const float*)d_in[15];
    const float* gw5 = (const float*)d_in[16]; const float* gb5 = (const float*)d_in[17];
    const float* lw1 = (const float*)d_in[18]; const float* lb1 = (const float*)d_in[19];
    const float* lw2 = (const float*)d_in[20]; const float* lb2 = (const float*)d_in[21];
    const float* hw1 = (const float*)d_in[22]; const float* hb1 = (const float*)d_in[23];
    const float* hw2 = (const float*)d_in[24]; const float* hb2 = (const float*)d_in[25];
    float* out = (float*)d_out;

    float *c1, *c2, *fmap, *ga, *gb_, *gcs, *gd, *ge, *Wcat, *biasC, *emb, *feat, *hid, *gcon;
    cudaGetSymbolAddress((void**)&c1, g_c1);
    cudaGetSymbolAddress((void**)&c2, g_c2);
    cudaGetSymbolAddress((void**)&fmap, g_fmap);
    cudaGetSymbolAddress((void**)&ga, g_ga);
    cudaGetSymbolAddress((void**)&gb_, g_gb);
    cudaGetSymbolAddress((void**)&gcs, g_gcs);
    cudaGetSymbolAddress((void**)&gd, g_gd);
    cudaGetSymbolAddress((void**)&ge, g_ge);
    cudaGetSymbolAddress((void**)&Wcat, g_Wcat);
    cudaGetSymbolAddress((void**)&biasC, g_biasC);
    cudaGetSymbolAddress((void**)&emb, g_embed);
    cudaGetSymbolAddress((void**)&feat, g_feat);
    cudaGetSymbolAddress((void**)&hid, g_hidden);
    cudaGetSymbolAddress((void**)&gcon, g_gcon);

    const int T = 256;
    auto blocks = [](int n) { return (n + 255) / 256; };

    // ----- plane encoder -----
    conv3x3_gelu<<<blocks(NB*16*112*112), T>>>(images, pw1, pb1, c1, NB, 3, 224, 224, 16, 112, 112, 2);
    conv3x3_gelu<<<blocks(NB*32*56*56),  T>>>(c1, pw2, pb2, c2, NB, 16, 112, 112, 32, 56, 56, 2);
    conv3x3_gelu<<<blocks(NB*4*56*56),   T>>>(c2, pw3, pb3, fmap, NB, 32, 56, 56, 4, 56, 56, 1);

    // ----- global encoder -----
    conv3x3_gelu<<<blocks(NB*4*112*112), T>>>(images, gw1, gb1, ga, NB, 3, 224, 224, 4, 112, 112, 2);
    conv3x3_gelu<<<blocks(NB*8*56*56),   T>>>(ga, gw2, gb2, gb_, NB, 4, 112, 112, 8, 56, 56, 2);
    conv3x3_gelu<<<blocks(NB*16*28*28),  T>>>(gb_, gw3, gb3, gcs, NB, 8, 56, 56, 16, 28, 28, 2);
    conv3x3_gelu<<<blocks(NB*32*14*14),  T>>>(gcs, gw4, gb4, gd, NB, 16, 28, 28, 32, 14, 14, 2);
    conv3x3_gelu<<<blocks(NB*64*7*7),    T>>>(gd, gw5, gb5, ge, NB, 32, 14, 14, 64, 7, 7, 2);
    gpool_kernel<<<blocks(NB*64), T>>>();

    // ----- fold weights / per-batch contributions -----
    prep_head<<<512, 256>>>(hw1, hb1, lw2, lb2);
    gcon_kernel<<<blocks(NB*512), T>>>(hw1);

    // ----- point branch: embed + GEMM1 into feat[:, 0:256] -----
    embed_kernel<<<blocks(MTOT*12), T>>>(points);
    {
        dim3 grid(256 / 128, MTOT / 128);
        sgemm128<<<grid, 256>>>(emb, 48, lw1, 48, feat, 512, lb1, nullptr);
    }

    // ----- patch gather into feat[:, 256:512] -----
    patch_kernel<<<blocks(MTOT*64), T>>>(points);

    // ----- head GEMM: hidden = gelu(feat @ Wcat^T + biasC + gcon[b]) -----
    {
        dim3 grid(512 / 128, MTOT / 128);
        sgemm128<<<grid, 256>>>(feat, 512, Wcat, 512, hid, 512, biasC, gcon);
    }

    // ----- final dot -----
    head_reduce<<<MTOT / 8, 256>>>(hw2, hb2, out);
}

// round 11
// speedup vs baseline: 1.0012x; 1.0012x over previous
#include <cuda_runtime.h>
#include <math.h>

#define NB 16
#define NPT 4096
#define MTOT (NB*NPT)   // 65536 points

__device__ __forceinline__ float gelu_f(float x) {
    return 0.5f * x * (1.0f + tanhf(0.7978845608028654f * (x + 0.044715f * x * x * x)));
}

// ---------------- scratch buffers (device globals; no allocs allowed) ----------------
__device__ float g_c1[NB*16*112*112];      // plane conv1 out
__device__ float g_c2[NB*32*56*56];        // plane conv2 out
__device__ float g_fmap[NB*4*56*56];       // plane conv3 out (fmap)
__device__ float g_ga[NB*4*112*112];       // global enc stages
__device__ float g_gb[NB*8*56*56];
__device__ float g_gcs[NB*16*28*28];
__device__ float g_gd[NB*32*14*14];
__device__ float g_ge[NB*64*7*7];
__device__ float g_gvec[NB*64];            // pooled global code
__device__ float g_gcon[NB*512];           // gc @ W_gc^T per batch
__device__ float g_Wcat[512*512];          // [Wcomb | W_patch]
__device__ float g_biasC[512];             // hb1 + W_pf @ lb2
__device__ float g_embed[MTOT*48];
__device__ float g_feat[(size_t)MTOT*512]; // [h2 | patches]
__device__ float g_hidden[(size_t)MTOT*512];

// ---------------- generic 3x3 conv, pad 1, stride s, gelu ----------------
__global__ void conv3x3_gelu(const float* __restrict__ in, const float* __restrict__ w,
                             const float* __restrict__ bias, float* __restrict__ out,
                             int B, int Cin, int Hin, int Win, int Cout, int Hout, int Wout,
                             int stride) {
    int idx = blockIdx.x * blockDim.x + threadIdx.x;
    int total = B * Cout * Hout * Wout;
    if (idx >= total) return;
    int ox = idx % Wout; int t = idx / Wout;
    int oy = t % Hout;   t /= Hout;
    int co = t % Cout;   int b = t / Cout;
    float acc = bias[co];
    const float* wp = w + co * Cin * 9;
    const float* ip = in + (size_t)b * Cin * Hin * Win;
    int iy0 = oy * stride - 1, ix0 = ox * stride - 1;
    for (int ci = 0; ci < Cin; ci++) {
        const float* ipc = ip + (size_t)ci * Hin * Win;
        const float* wpc = wp + ci * 9;
        #pragma unroll
        for (int ky = 0; ky < 3; ky++) {
            int iy = iy0 + ky;
            if (iy < 0 || iy >= Hin) continue;
            #pragma unroll
            for (int kx = 0; kx < 3; kx++) {
                int ix = ix0 + kx;
                if (ix < 0 || ix >= Win) continue;
                acc += ipc[iy * Win + ix] * wpc[ky * 3 + kx];
            }
        }
    }
    out[idx] = gelu_f(acc);
}

// ---------------- global pooling: mean over 7x7 ----------------
__global__ void gpool_kernel() {
    int idx = blockIdx.x * blockDim.x + threadIdx.x;  // 16*64
    if (idx >= NB * 64) return;
    const float* p = g_ge + idx * 49;
    float s = 0.f;
    #pragma unroll
    for (int i = 0; i < 49; i++) s += p[i];
    g_gvec[idx] = s * (1.0f / 49.0f);
}

// ---------------- per-batch gc contribution: gcon[b,j] = sum_c gc[b,c]*hw1[j,512+c] ----
__global__ void gcon_kernel(const float* __restrict__ hw1) {
    int idx = blockIdx.x * blockDim.x + threadIdx.x;  // 16*512
    if (idx >= NB * 512) return;
    int b = idx >> 9, j = idx & 511;
    float acc = 0.f;
    const float* gv = g_gvec + b * 64;
    const float* hp = hw1 + j * 576 + 512;
    #pragma unroll
    for (int c = 0; c < 64; c++) acc += gv[c] * hp[c];
    g_gcon[idx] = acc;
}

// ---------------- head weight prep: Wcat = [hw1[:,0:256]@lw2 | hw1[:,256:512]] --------
__global__ void prep_head(const float* __restrict__ hw1, const float* __restrict__ hb1,
                          const float* __restrict__ lw2, const float* __restrict__ lb2) {
    int j = blockIdx.x;       // 512
    int t = threadIdx.x;      // 256
    const float* hrow = hw1 + j * 576;
    float acc = 0.f;
    for (int c = 0; c < 256; c++)
        acc += hrow[c] * lw2[c * 256 + t];
    g_Wcat[j * 512 + t] = acc;
    g_Wcat[j * 512 + 256 + t] = hrow[256 + t];
    __shared__ float s[256];
    s[t] = hrow[t] * lb2[t];
    __syncthreads();
    for (int o = 128; o > 0; o >>= 1) {
        if (t < o) s[t] += s[t + o];
        __syncthreads();
    }
    if (t == 0) g_biasC[j] = hb1[j] + s[0];
}

// ---------------- positional embedding ----------------
__global__ void embed_kernel(const float* __restrict__ points) {
    int idx = blockIdx.x * blockDim.x + threadIdx.x;  // MTOT*12
    if (idx >= MTOT * 12) return;
    int m = idx / 12, i = idx % 12;
    float f = (float)(1 << i);
    float px = points[m * 2 + 0], py = points[m * 2 + 1];
    float sx, cx, sy, cy;
    sincosf(f * px, &sx, &cx);
    sincosf(f * py, &sy, &cy);
    float* e = g_embed + m * 48 + 4 * i;
    e[0] = sx; e[1] = sy; e[2] = cx; e[3] = cy;
}

// ---------------- bilinear patch gather into g_feat cols [256,512) -------------------
__global__ void patch_kernel(const float* __restrict__ points) {
    int idx = blockIdx.x * blockDim.x + threadIdx.x;  // MTOT*64
    if (idx >= MTOT * 64) return;
    int pp = idx & 63;
    int m = idx >> 6;
    int i = pp >> 3, j = pp & 7;          // i -> x offset, j -> y offset
    int b = m >> 12;
    float px = points[m * 2 + 0], py = points[m * 2 + 1];
    const float step = 2.0f / 55.0f;
    float gx = (px * 2.0f - 1.0f) + ((float)i - 3.5f) * step;
    float gy = (py * 2.0f - 1.0f) + ((float)j - 3.5f) * step;
    float ix = (gx + 1.0f) * 0.5f * 55.0f;
    float iy = (gy + 1.0f) * 0.5f * 55.0f;
    float x0f = floorf(ix), y0f = floorf(iy);
    int x0 = (int)x0f, y0 = (int)y0f;
    int x1 = x0 + 1, y1 = y0 + 1;
    float wx1 = ix - x0f, wx0 = 1.0f - wx1;
    float wy1 = iy - y0f, wy0 = 1.0f - wy1;
    bool vx0 = (x0 >= 0) & (x0 < 56), vx1 = (x1 >= 0) & (x1 < 56);
    bool vy0 = (y0 >= 0) & (y0 < 56), vy1 = (y1 >= 0) & (y1 < 56);
    int cx0 = min(max(x0, 0), 55), cx1 = min(max(x1, 0), 55);
    int cy0 = min(max(y0, 0), 55), cy1 = min(max(y1, 0), 55);
    float w00 = wx0 * wy0 * ((vx0 && vy0) ? 1.f : 0.f);
    float w10 = wx1 * wy0 * ((vx1 && vy0) ? 1.f : 0.f);
    float w01 = wx0 * wy1 * ((vx0 && vy1) ? 1.f : 0.f);
    float w11 = wx1 * wy1 * ((vx1 && vy1) ? 1.f : 0.f);
    int i00 = cy0 * 56 + cx0, i10 = cy0 * 56 + cx1;
    int i01 = cy1 * 56 + cx0, i11 = cy1 * 56 + cx1;
    const float* fm = g_fmap + (size_t)b * 4 * 3136;
    float* fo = g_feat + (size_t)m * 512 + 256 + pp;
    #pragma unroll
    for (int c = 0; c < 4; c++) {
        const float* base = fm + c * 3136;
        float v = w00 * base[i00] + w10 * base[i10] + w01 * base[i01] + w11 * base[i11];
        fo[c * 64] = v;
    }
}

// ---------------- tiled SGEMM: C[M,N] = gelu(A[M,K] @ W[N,K]^T + bias (+ gcon)) ------
// BM=BN=128, BK=8, 256 threads, 8x8 per thread
__global__ __launch_bounds__(256) void sgemm128(
    const float* __restrict__ A, int lda,
    const float* __restrict__ W, int K,
    float* __restrict__ C, int ldc,
    const float* __restrict__ bias,
    const float* __restrict__ gcon) {
    __shared__ float As[8][128];
    __shared__ float Bs[8][128];
    int tid = threadIdx.x;
    int blockM = blockIdx.y * 128;
    int blockN = blockIdx.x * 128;
    int ty = tid >> 4, tx = tid & 15;
    int arow = tid >> 1;
    int acol = (tid & 1) * 4;
    const float* Aptr = A + (size_t)(blockM + arow) * lda + acol;
    const float* Wptr = W + (size_t)(blockN + arow) * K + acol;

    float acc[8][8];
    #pragma unroll
    for (int i = 0; i < 8; i++)
        #pragma unroll
        for (int j = 0; j < 8; j++) acc[i][j] = 0.f;

    for (int k0 = 0; k0 < K; k0 += 8) {
        float4 av = *reinterpret_cast<const float4*>(Aptr + k0);
        float4 wv = *reinterpret_cast<const float4*>(Wptr + k0);
        As[acol + 0][arow] = av.x; As[acol + 1][arow] = av.y;
        As[acol + 2][arow] = av.z; As[acol + 3][arow] = av.w;
        Bs[acol + 0][arow] = wv.x; Bs[acol + 1][arow] = wv.y;
        Bs[acol + 2][arow] = wv.z; Bs[acol + 3][arow] = wv.w;
        __syncthreads();
        #pragma unroll
        for (int k = 0; k < 8; k++) {
            float a[8], bb[8];
            #pragma unroll
            for (int i = 0; i < 8; i++) a[i] = As[k][ty * 8 + i];
            #pragma unroll
            for (int j = 0; j < 8; j++) bb[j] = Bs[k][tx * 8 + j];
            #pragma unroll
            for (int i = 0; i < 8; i++)
                #pragma unroll
                for (int j = 0; j < 8; j++)
                    acc[i][j] += a[i] * bb[j];
        }
        __syncthreads();
    }
    #pragma unroll
    for (int i = 0; i < 8; i++) {
        int row = blockM + ty * 8 + i;
        const float* grow = gcon ? (gcon + (size_t)(row >> 12) * 512) : nullptr;
        float* crow = C + (size_t)row * ldc;
        #pragma unroll
        for (int j = 0; j < 8; j++) {
            int col = blockN + tx * 8 + j;
            float v = acc[i][j] + bias[col];
            if (grow) v += grow[col];
            crow[col] = gelu_f(v);
        }
    }
}

// ---------------- final dot with hw2 ----------------
__global__ void head_reduce(const float* __restrict__ hw2, const float* __restrict__ hb2,
                            float* __restrict__ out) {
    int m = blockIdx.x * 8 + (threadIdx.x >> 5);
    int lane = threadIdx.x & 31;
    const float* h = g_hidden + (size_t)m * 512;
    float s = 0.f;
    #pragma unroll
    for (int j0 = 0; j0 < 512; j0 += 32)
        s += h[j0 + lane] * hw2[j0 + lane];
    #pragma unroll
    for (int o = 16; o > 0; o >>= 1) s += __shfl_xor_sync(0xFFFFFFFFu, s, o);
    if (lane == 0) out[m] = s + hb2[0];
}

// =====================================================================================
extern "C" void kernel_launch(void* const* d_in, const int* in_sizes, int n_in,
                              void* d_out, int out_size) {
    const float* points = (const float*)d_in[0];
    const float* images = (const float*)d_in[1];
    const float* pw1 = (const float*)d_in[2];  const float* pb1 = (const float*)d_in[3];
    const float* pw2 = (const float*)d_in[4];  const float* pb2 = (const float*)d_in[5];
    const float* pw3 = (const float*)d_in[6];  const float* pb3 = (const float*)d_in[7];
    const float* gw1 = (const float*)d_in[8];  const float* gb1 = (const float*)d_in[9];
    const float* gw2 = (const float*)d_in[10]; const float* gb2 = (const float*)d_in[11];
    const float* gw3 = (const float*)d_in[12]; const float* gb3 = (const float*)d_in[13];
    const float* gw4 = (const float*)d_in[14]; const float* gb4 = (const float*)d_in[15];
    const float* gw5 = (const float*)d_in[16]; const float* gb5 = (const float*)d_in[17];
    const float* lw1 = (const float*)d_in[18]; const float* lb1 = (const float*)d_in[19];
    const float* lw2 = (const float*)d_in[20]; const float* lb2 = (const float*)d_in[21];
    const float* hw1 = (const float*)d_in[22]; const float* hb1 = (const float*)d_in[23];
    const float* hw2 = (const float*)d_in[24]; const float* hb2 = (const float*)d_in[25];
    float* out = (float*)d_out;

    float *c1, *c2, *fmap, *ga, *gb_, *gcs, *gd, *ge, *Wcat, *biasC, *emb, *feat, *hid, *gcon;
    cudaGetSymbolAddress((void**)&c1, g_c1);
    cudaGetSymbolAddress((void**)&c2, g_c2);
    cudaGetSymbolAddress((void**)&fmap, g_fmap);
    cudaGetSymbolAddress((void**)&ga, g_ga);
    cudaGetSymbolAddress((void**)&gb_, g_gb);
    cudaGetSymbolAddress((void**)&gcs, g_gcs);
    cudaGetSymbolAddress((void**)&gd, g_gd);
    cudaGetSymbolAddress((void**)&ge, g_ge);
    cudaGetSymbolAddress((void**)&Wcat, g_Wcat);
    cudaGetSymbolAddress((void**)&biasC, g_biasC);
    cudaGetSymbolAddress((void**)&emb, g_embed);
    cudaGetSymbolAddress((void**)&feat, g_feat);
    cudaGetSymbolAddress((void**)&hid, g_hidden);
    cudaGetSymbolAddress((void**)&gcon, g_gcon);

    const int T = 256;
    auto blocks = [](int n) { return (n + 255) / 256; };

    // ----- plane encoder -----
    conv3x3_gelu<<<blocks(NB*16*112*112), T>>>(images, pw1, pb1, c1, NB, 3, 224, 224, 16, 112, 112, 2);
    conv3x3_gelu<<<blocks(NB*32*56*56),  T>>>(c1, pw2, pb2, c2, NB, 16, 112, 112, 32, 56, 56, 2);
    conv3x3_gelu<<<blocks(NB*4*56*56),   T>>>(c2, pw3, pb3, fmap, NB, 32, 56, 56, 4, 56, 56, 1);

    // ----- global encoder -----
    conv3x3_gelu<<<blocks(NB*4*112*112), T>>>(images, gw1, gb1, ga, NB, 3, 224, 224, 4, 112, 112, 2);
    conv3x3_gelu<<<blocks(NB*8*56*56),   T>>>(ga, gw2, gb2, gb_, NB, 4, 112, 112, 8, 56, 56, 2);
    conv3x3_gelu<<<blocks(NB*16*28*28),  T>>>(gb_, gw3, gb3, gcs, NB, 8, 56, 56, 16, 28, 28, 2);
    conv3x3_gelu<<<blocks(NB*32*14*14),  T>>>(gcs, gw4, gb4, gd, NB, 16, 28, 28, 32, 14, 14, 2);
    conv3x3_gelu<<<blocks(NB*64*7*7),    T>>>(gd, gw5, gb5, ge, NB, 32, 14, 14, 64, 7, 7, 2);
    gpool_kernel<<<blocks(NB*64), T>>>();

    // ----- fold weights / per-batch contributions -----
    prep_head<<<512, 256>>>(hw1, hb1, lw2, lb2);
    gcon_kernel<<<blocks(NB*512), T>>>(hw1);

    // ----- point branch: embed + GEMM1 into feat[:, 0:256] -----
    embed_kernel<<<blocks(MTOT*12), T>>>(points);
    {
        dim3 grid(256 / 128, MTOT / 128);
        sgemm128<<<grid, 256>>>(emb, 48, lw1, 48, feat, 512, lb1, nullptr);
    }

    // ----- patch gather into feat[:, 256:512] -----
    patch_kernel<<<blocks(MTOT*64), T>>>(points);

    // ----- head GEMM: hidden = gelu(feat @ Wcat^T + biasC + gcon[b]) -----
    {
        dim3 grid(512 / 128, MTOT / 128);
        sgemm128<<<grid, 256>>>(feat, 512, Wcat, 512, hid, 512, biasC, gcon);
    }

    // ----- final dot -----
    head_reduce<<<MTOT / 8, 256>>>(hw2, hb2, out);
}

// round 12
// speedup vs baseline: 1.7368x; 1.7348x over previous
#include <cuda_runtime.h>
#include <math.h>
#include <stdint.h>

#define NB 16
#define NPT 4096
#define MTOT (NB*NPT)   // 65536 points

__device__ __forceinline__ float gelu_f(float x) {
    return 0.5f * x * (1.0f + tanhf(0.7978845608028654f * (x + 0.044715f * x * x * x)));
}

__device__ __forceinline__ uint32_t f2tf32(float x) {
    uint32_t u;
    asm("cvt.rna.tf32.f32 %0, %1;" : "=r"(u) : "f"(x));
    return u;
}

// ---------------- scratch buffers (device globals; no allocs allowed) ----------------
__device__ float g_c1[NB*16*112*112];      // plane conv1 out
__device__ float g_c2[NB*32*56*56];        // plane conv2 out
__device__ float g_fmap[NB*4*56*56];       // plane conv3 out (fmap)
__device__ float g_ga[NB*4*112*112];       // global enc stages
__device__ float g_gb[NB*8*56*56];
__device__ float g_gcs[NB*16*28*28];
__device__ float g_gd[NB*32*14*14];
__device__ float g_ge[NB*64*7*7];
__device__ float g_gvec[NB*64];            // pooled global code
__device__ float g_gcon[NB*512];           // gc @ W_gc^T per batch
__device__ float g_Wcat[512*512];          // [Wcomb | W_patch]
__device__ float g_biasC[512];             // hb1 + W_pf @ lb2
__device__ float g_embed[MTOT*48];
__device__ float g_feat[(size_t)MTOT*512]; // [h2 | patches]

// ---------------- generic 3x3 conv, pad 1, stride s, gelu ----------------
__global__ void conv3x3_gelu(const float* __restrict__ in, const float* __restrict__ w,
                             const float* __restrict__ bias, float* __restrict__ out,
                             int B, int Cin, int Hin, int Win, int Cout, int Hout, int Wout,
                             int stride) {
    int idx = blockIdx.x * blockDim.x + threadIdx.x;
    int total = B * Cout * Hout * Wout;
    if (idx >= total) return;
    int ox = idx % Wout; int t = idx / Wout;
    int oy = t % Hout;   t /= Hout;
    int co = t % Cout;   int b = t / Cout;
    float acc = bias[co];
    const float* wp = w + co * Cin * 9;
    const float* ip = in + (size_t)b * Cin * Hin * Win;
    int iy0 = oy * stride - 1, ix0 = ox * stride - 1;
    for (int ci = 0; ci < Cin; ci++) {
        const float* ipc = ip + (size_t)ci * Hin * Win;
        const float* wpc = wp + ci * 9;
        #pragma unroll
        for (int ky = 0; ky < 3; ky++) {
            int iy = iy0 + ky;
            if (iy < 0 || iy >= Hin) continue;
            #pragma unroll
            for (int kx = 0; kx < 3; kx++) {
                int ix = ix0 + kx;
                if (ix < 0 || ix >= Win) continue;
                acc += ipc[iy * Win + ix] * wpc[ky * 3 + kx];
            }
        }
    }
    out[idx] = gelu_f(acc);
}

// ---------------- global pooling: mean over 7x7 ----------------
__global__ void gpool_kernel() {
    int idx = blockIdx.x * blockDim.x + threadIdx.x;  // 16*64
    if (idx >= NB * 64) return;
    const float* p = g_ge + idx * 49;
    float s = 0.f;
    #pragma unroll
    for (int i = 0; i < 49; i++) s += p[i];
    g_gvec[idx] = s * (1.0f / 49.0f);
}

// ---------------- per-batch gc contribution ----------------
__global__ void gcon_kernel(const float* __restrict__ hw1) {
    int idx = blockIdx.x * blockDim.x + threadIdx.x;  // 16*512
    if (idx >= NB * 512) return;
    int b = idx >> 9, j = idx & 511;
    float acc = 0.f;
    const float* gv = g_gvec + b * 64;
    const float* hp = hw1 + j * 576 + 512;
    #pragma unroll
    for (int c = 0; c < 64; c++) acc += gv[c] * hp[c];
    g_gcon[idx] = acc;
}

// ---------------- head weight prep: Wcat = [hw1[:,0:256]@lw2 | hw1[:,256:512]] --------
__global__ void prep_head(const float* __restrict__ hw1, const float* __restrict__ hb1,
                          const float* __restrict__ lw2, const float* __restrict__ lb2) {
    int j = blockIdx.x;       // 512
    int t = threadIdx.x;      // 256
    const float* hrow = hw1 + j * 576;
    float acc = 0.f;
    for (int c = 0; c < 256; c++)
        acc += hrow[c] * lw2[c * 256 + t];
    g_Wcat[j * 512 + t] = acc;
    g_Wcat[j * 512 + 256 + t] = hrow[256 + t];
    __shared__ float s[256];
    s[t] = hrow[t] * lb2[t];
    __syncthreads();
    for (int o = 128; o > 0; o >>= 1) {
        if (t < o) s[t] += s[t + o];
        __syncthreads();
    }
    if (t == 0) g_biasC[j] = hb1[j] + s[0];
}

// ---------------- positional embedding ----------------
__global__ void embed_kernel(const float* __restrict__ points) {
    int idx = blockIdx.x * blockDim.x + threadIdx.x;  // MTOT*12
    if (idx >= MTOT * 12) return;
    int m = idx / 12, i = idx % 12;
    float f = (float)(1 << i);
    float px = points[m * 2 + 0], py = points[m * 2 + 1];
    float sx, cx, sy, cy;
    sincosf(f * px, &sx, &cx);
    sincosf(f * py, &sy, &cy);
    float* e = g_embed + m * 48 + 4 * i;
    e[0] = sx; e[1] = sy; e[2] = cx; e[3] = cy;
}

// ---------------- bilinear patch gather into g_feat cols [256,512) -------------------
__global__ void patch_kernel(const float* __restrict__ points) {
    int idx = blockIdx.x * blockDim.x + threadIdx.x;  // MTOT*64
    if (idx >= MTOT * 64) return;
    int pp = idx & 63;
    int m = idx >> 6;
    int i = pp >> 3, j = pp & 7;
    int b = m >> 12;
    float px = points[m * 2 + 0], py = points[m * 2 + 1];
    const float step = 2.0f / 55.0f;
    float gx = (px * 2.0f - 1.0f) + ((float)i - 3.5f) * step;
    float gy = (py * 2.0f - 1.0f) + ((float)j - 3.5f) * step;
    float ix = (gx + 1.0f) * 0.5f * 55.0f;
    float iy = (gy + 1.0f) * 0.5f * 55.0f;
    float x0f = floorf(ix), y0f = floorf(iy);
    int x0 = (int)x0f, y0 = (int)y0f;
    int x1 = x0 + 1, y1 = y0 + 1;
    float wx1 = ix - x0f, wx0 = 1.0f - wx1;
    float wy1 = iy - y0f, wy0 = 1.0f - wy1;
    bool vx0 = (x0 >= 0) & (x0 < 56), vx1 = (x1 >= 0) & (x1 < 56);
    bool vy0 = (y0 >= 0) & (y0 < 56), vy1 = (y1 >= 0) & (y1 < 56);
    int cx0 = min(max(x0, 0), 55), cx1 = min(max(x1, 0), 55);
    int cy0 = min(max(y0, 0), 55), cy1 = min(max(y1, 0), 55);
    float w00 = wx0 * wy0 * ((vx0 && vy0) ? 1.f : 0.f);
    float w10 = wx1 * wy0 * ((vx1 && vy0) ? 1.f : 0.f);
    float w01 = wx0 * wy1 * ((vx0 && vy1) ? 1.f : 0.f);
    float w11 = wx1 * wy1 * ((vx1 && vy1) ? 1.f : 0.f);
    int i00 = cy0 * 56 + cx0, i10 = cy0 * 56 + cx1;
    int i01 = cy1 * 56 + cx0, i11 = cy1 * 56 + cx1;
    const float* fm = g_fmap + (size_t)b * 4 * 3136;
    float* fo = g_feat + (size_t)m * 512 + 256 + pp;
    #pragma unroll
    for (int c = 0; c < 4; c++) {
        const float* base = fm + c * 3136;
        float v = w00 * base[i00] + w10 * base[i10] + w01 * base[i01] + w11 * base[i11];
        fo[c * 64] = v;
    }
}

// ---------------- fp32 tiled SGEMM for GEMM1 (K=48) ----------------
__global__ __launch_bounds__(256) void sgemm128(
    const float* __restrict__ A, int lda,
    const float* __restrict__ W, int K,
    float* __restrict__ C, int ldc,
    const float* __restrict__ bias) {
    __shared__ float As[8][128];
    __shared__ float Bs[8][128];
    int tid = threadIdx.x;
    int blockM = blockIdx.y * 128;
    int blockN = blockIdx.x * 128;
    int ty = tid >> 4, tx = tid & 15;
    int arow = tid >> 1;
    int acol = (tid & 1) * 4;
    const float* Aptr = A + (size_t)(blockM + arow) * lda + acol;
    const float* Wptr = W + (size_t)(blockN + arow) * K + acol;

    float acc[8][8];
    #pragma unroll
    for (int i = 0; i < 8; i++)
        #pragma unroll
        for (int j = 0; j < 8; j++) acc[i][j] = 0.f;

    for (int k0 = 0; k0 < K; k0 += 8) {
        float4 av = *reinterpret_cast<const float4*>(Aptr + k0);
        float4 wv = *reinterpret_cast<const float4*>(Wptr + k0);
        As[acol + 0][arow] = av.x; As[acol + 1][arow] = av.y;
        As[acol + 2][arow] = av.z; As[acol + 3][arow] = av.w;
        Bs[acol + 0][arow] = wv.x; Bs[acol + 1][arow] = wv.y;
        Bs[acol + 2][arow] = wv.z; Bs[acol + 3][arow] = wv.w;
        __syncthreads();
        #pragma unroll
        for (int k = 0; k < 8; k++) {
            float a[8], bb[8];
            #pragma unroll
            for (int i = 0; i < 8; i++) a[i] = As[k][ty * 8 + i];
            #pragma unroll
            for (int j = 0; j < 8; j++) bb[j] = Bs[k][tx * 8 + j];
            #pragma unroll
            for (int i = 0; i < 8; i++)
                #pragma unroll
                for (int j = 0; j < 8; j++)
                    acc[i][j] += a[i] * bb[j];
        }
        __syncthreads();
    }
    #pragma unroll
    for (int i = 0; i < 8; i++) {
        int row = blockM + ty * 8 + i;
        float* crow = C + (size_t)row * ldc;
        #pragma unroll
        for (int j = 0; j < 8; j++) {
            int col = blockN + tx * 8 + j;
            crow[col] = gelu_f(acc[i][j] + bias[col]);
        }
    }
}

// ---------------- out init: out[m] = hb2[0] ----------------
__global__ void init_out(float* __restrict__ out, const float* __restrict__ hb2) {
    int i = blockIdx.x * blockDim.x + threadIdx.x;
    if (i < MTOT) out[i] = hb2[0];
}

// =====================================================================================
// TF32 tensor-core GEMM2 with fused head reduction:
//   out[m] += sum_j gelu( feat[m,:] . Wcat[j,:] + biasC[j] + gcon[b(m),j] ) * hw2[j]
// Block tile 128x128, K-chunk 32, 256 threads (8 warps, 2x4 warp grid, 64x32 per warp)
// =====================================================================================
#define SMS 132   // padded smem stride (row dim)

__global__ __launch_bounds__(256) void gemm2_tf32_fused(
    const float* __restrict__ A,        // g_feat [M,512]
    const float* __restrict__ W,        // g_Wcat [512,512]
    const float* __restrict__ bias,     // g_biasC [512]
    const float* __restrict__ gcon,     // g_gcon [16,512]
    const float* __restrict__ hw2,      // [512]
    float* __restrict__ out) {          // [M]
    __shared__ uint32_t As[32 * SMS];
    __shared__ uint32_t Bs[32 * SMS];

    const int tid = threadIdx.x;
    const int lane = tid & 31;
    const int warpId = tid >> 5;
    const int warpM = warpId & 1;        // 0..1
    const int warpN = warpId >> 1;       // 0..3
    const int tg = lane & 3;             // thread-in-group
    const int gid = lane >> 2;           // group id 0..7

    const int blockM = blockIdx.y * 128;
    const int blockN = blockIdx.x * 128;
    const int batch = blockM >> 12;

    // load indices: 4 float4 per thread per operand per K-chunk
    // lin = r*256+tid -> row = lin>>3 (0..127), c4 = lin&7 (cols c4*4..+3)
    float4 pa[4], pb[4];

    auto loadg = [&](int k0) {
        #pragma unroll
        for (int r = 0; r < 4; r++) {
            int lin = r * 256 + tid;
            int row = lin >> 3, c4 = lin & 7;
            pa[r] = *reinterpret_cast<const float4*>(A + (size_t)(blockM + row) * 512 + k0 + c4 * 4);
            pb[r] = *reinterpret_cast<const float4*>(W + (size_t)(blockN + row) * 512 + k0 + c4 * 4);
        }
    };
    auto stores = [&]() {
        #pragma unroll
        for (int r = 0; r < 4; r++) {
            int lin = r * 256 + tid;
            int row = lin >> 3, c4 = lin & 7;
            As[(c4 * 4 + 0) * SMS + row] = f2tf32(pa[r].x);
            As[(c4 * 4 + 1) * SMS + row] = f2tf32(pa[r].y);
            As[(c4 * 4 + 2) * SMS + row] = f2tf32(pa[r].z);
            As[(c4 * 4 + 3) * SMS + row] = f2tf32(pa[r].w);
            Bs[(c4 * 4 + 0) * SMS + row] = f2tf32(pb[r].x);
            Bs[(c4 * 4 + 1) * SMS + row] = f2tf32(pb[r].y);
            Bs[(c4 * 4 + 2) * SMS + row] = f2tf32(pb[r].z);
            Bs[(c4 * 4 + 3) * SMS + row] = f2tf32(pb[r].w);
        }
    };

    float acc[4][4][4];
    #pragma unroll
    for (int mi = 0; mi < 4; mi++)
        #pragma unroll
        for (int ni = 0; ni < 4; ni++)
            #pragma unroll
            for (int c = 0; c < 4; c++) acc[mi][ni][c] = 0.f;

    loadg(0);
    stores();
    __syncthreads();

    const int rowB = warpM * 64;
    const int colB = warpN * 32;

    for (int kt = 0; kt < 16; kt++) {
        if (kt < 15) loadg((kt + 1) * 32);
        #pragma unroll
        for (int kk = 0; kk < 4; kk++) {
            int k = kk * 8;
            uint32_t af[4][4];
            #pragma unroll
            for (int mi = 0; mi < 4; mi++) {
                int r0 = rowB + mi * 16 + gid;
                af[mi][0] = As[(k + tg) * SMS + r0];
                af[mi][1] = As[(k + tg) * SMS + r0 + 8];
                af[mi][2] = As[(k + tg + 4) * SMS + r0];
                af[mi][3] = As[(k + tg + 4) * SMS + r0 + 8];
            }
            uint32_t bf[4][2];
            #pragma unroll
            for (int ni = 0; ni < 4; ni++) {
                int c0 = colB + ni * 8 + gid;
                bf[ni][0] = Bs[(k + tg) * SMS + c0];
                bf[ni][1] = Bs[(k + tg + 4) * SMS + c0];
            }
            #pragma unroll
            for (int mi = 0; mi < 4; mi++)
                #pragma unroll
                for (int ni = 0; ni < 4; ni++) {
                    asm volatile(
                        "mma.sync.aligned.m16n8k8.row.col.f32.tf32.tf32.f32 "
                        "{%0,%1,%2,%3}, {%4,%5,%6,%7}, {%8,%9}, {%0,%1,%2,%3};"
                        : "+f"(acc[mi][ni][0]), "+f"(acc[mi][ni][1]),
                          "+f"(acc[mi][ni][2]), "+f"(acc[mi][ni][3])
                        : "r"(af[mi][0]), "r"(af[mi][1]), "r"(af[mi][2]), "r"(af[mi][3]),
                          "r"(bf[ni][0]), "r"(bf[ni][1]));
                }
        }
        __syncthreads();
        if (kt < 15) {
            stores();
            __syncthreads();
        }
    }

    // ---- fused epilogue: gelu(+bias+gcon) * hw2, row-reduce, atomicAdd ----
    // thread's columns: for ni in 0..3: c = blockN + colB + ni*8 + tg*2 + {0,1}
    float addc[8], w2c[8];
    #pragma unroll
    for (int ni = 0; ni < 4; ni++) {
        int c0 = blockN + colB + ni * 8 + tg * 2;
        addc[ni * 2 + 0] = bias[c0] + gcon[batch * 512 + c0];
        addc[ni * 2 + 1] = bias[c0 + 1] + gcon[batch * 512 + c0 + 1];
        w2c[ni * 2 + 0] = hw2[c0];
        w2c[ni * 2 + 1] = hw2[c0 + 1];
    }
    #pragma unroll
    for (int mi = 0; mi < 4; mi++) {
        float s0 = 0.f, s1 = 0.f;   // rows r0, r0+8
        #pragma unroll
        for (int ni = 0; ni < 4; ni++) {
            s0 += gelu_f(acc[mi][ni][0] + addc[ni * 2 + 0]) * w2c[ni * 2 + 0];
            s0 += gelu_f(acc[mi][ni][1] + addc[ni * 2 + 1]) * w2c[ni * 2 + 1];
            s1 += gelu_f(acc[mi][ni][2] + addc[ni * 2 + 0]) * w2c[ni * 2 + 0];
            s1 += gelu_f(acc[mi][ni][3] + addc[ni * 2 + 1]) * w2c[ni * 2 + 1];
        }
        // reduce across the 4 threads in the row group (lanes l, l^1, l^2)
        s0 += __shfl_xor_sync(0xFFFFFFFFu, s0, 1);
        s0 += __shfl_xor_sync(0xFFFFFFFFu, s0, 2);
        s1 += __shfl_xor_sync(0xFFFFFFFFu, s1, 1);
        s1 += __shfl_xor_sync(0xFFFFFFFFu, s1, 2);
        if (tg == 0) {
            int r0 = blockM + rowB + mi * 16 + gid;
            atomicAdd(out + r0, s0);
            atomicAdd(out + r0 + 8, s1);
        }
    }
}

// =====================================================================================
extern "C" void kernel_launch(void* const* d_in, const int* in_sizes, int n_in,
                              void* d_out, int out_size) {
    const float* points = (const float*)d_in[0];
    const float* images = (const float*)d_in[1];
    const float* pw1 = (const float*)d_in[2];  const float* pb1 = (const float*)d_in[3];
    const float* pw2 = (const float*)d_in[4];  const float* pb2 = (const float*)d_in[5];
    const float* pw3 = (const float*)d_in[6];  const float* pb3 = (const float*)d_in[7];
    const float* gw1 = (const float*)d_in[8];  const float* gb1 = (const float*)d_in[9];
    const float* gw2 = (const float*)d_in[10]; const float* gb2 = (const float*)d_in[11];
    const float* gw3 = (const float*)d_in[12]; const float* gb3 = (const float*)d_in[13];
    const float* gw4 = (const float*)d_in[14]; const float* gb4 = (const float*)d_in[15];
    const float* gw5 = (const float*)d_in[16]; const float* gb5 = (const float*)d_in[17];
    const float* lw1 = (const float*)d_in[18]; const float* lb1 = (const float*)d_in[19];
    const float* lw2 = (const float*)d_in[20]; const float* lb2 = (const float*)d_in[21];
    const float* hw1 = (const float*)d_in[22]; const float* hb1 = (const float*)d_in[23];
    const float* hw2 = (const float*)d_in[24]; const float* hb2 = (const float*)d_in[25];
    float* out = (float*)d_out;

    float *c1, *c2, *fmap, *ga, *gb_, *gcs, *gd, *ge, *Wcat, *biasC, *emb, *feat, *gcon;
    cudaGetSymbolAddress((void**)&c1, g_c1);
    cudaGetSymbolAddress((void**)&c2, g_c2);
    cudaGetSymbolAddress((void**)&fmap, g_fmap);
    cudaGetSymbolAddress((void**)&ga, g_ga);
    cudaGetSymbolAddress((void**)&gb_, g_gb);
    cudaGetSymbolAddress((void**)&gcs, g_gcs);
    cudaGetSymbolAddress((void**)&gd, g_gd);
    cudaGetSymbolAddress((void**)&ge, g_ge);
    cudaGetSymbolAddress((void**)&Wcat, g_Wcat);
    cudaGetSymbolAddress((void**)&biasC, g_biasC);
    cudaGetSymbolAddress((void**)&emb, g_embed);
    cudaGetSymbolAddress((void**)&feat, g_feat);
    cudaGetSymbolAddress((void**)&gcon, g_gcon);

    const int T = 256;
    auto blocks = [](int n) { return (n + 255) / 256; };

    // ----- plane encoder -----
    conv3x3_gelu<<<blocks(NB*16*112*112), T>>>(images, pw1, pb1, c1, NB, 3, 224, 224, 16, 112, 112, 2);
    conv3x3_gelu<<<blocks(NB*32*56*56),  T>>>(c1, pw2, pb2, c2, NB, 16, 112, 112, 32, 56, 56, 2);
    conv3x3_gelu<<<blocks(NB*4*56*56),   T>>>(c2, pw3, pb3, fmap, NB, 32, 56, 56, 4, 56, 56, 1);

    // ----- global encoder -----
    conv3x3_gelu<<<blocks(NB*4*112*112), T>>>(images, gw1, gb1, ga, NB, 3, 224, 224, 4, 112, 112, 2);
    conv3x3_gelu<<<blocks(NB*8*56*56),   T>>>(ga, gw2, gb2, gb_, NB, 4, 112, 112, 8, 56, 56, 2);
    conv3x3_gelu<<<blocks(NB*16*28*28),  T>>>(gb_, gw3, gb3, gcs, NB, 8, 56, 56, 16, 28, 28, 2);
    conv3x3_gelu<<<blocks(NB*32*14*14),  T>>>(gcs, gw4, gb4, gd, NB, 16, 28, 28, 32, 14, 14, 2);
    conv3x3_gelu<<<blocks(NB*64*7*7),    T>>>(gd, gw5, gb5, ge, NB, 32, 14, 14, 64, 7, 7, 2);
    gpool_kernel<<<blocks(NB*64), T>>>();

    // ----- fold weights / per-batch contributions -----
    prep_head<<<512, 256>>>(hw1, hb1, lw2, lb2);
    gcon_kernel<<<blocks(NB*512), T>>>(hw1);

    // ----- point branch: embed + GEMM1 into feat[:, 0:256] -----
    embed_kernel<<<blocks(MTOT*12), T>>>(points);
    {
        dim3 grid(256 / 128, MTOT / 128);
        sgemm128<<<grid, 256>>>(emb, 48, lw1, 48, feat, 512, lb1);
    }

    // ----- patch gather into feat[:, 256:512] -----
    patch_kernel<<<blocks(MTOT*64), T>>>(points);

    // ----- head GEMM (tf32 tensor cores) fused with final reduction -----
    init_out<<<blocks(MTOT), T>>>(out, hb2);
    {
        dim3 grid(512 / 128, MTOT / 128);
        gemm2_tf32_fused<<<grid, 256>>>(feat, Wcat, biasC, gcon, hw2, out);
    }
}

// round 13
// speedup vs baseline: 1.7732x; 1.0210x over previous
#include <cuda_runtime.h>
#include <math.h>
#include <stdint.h>

#define NB 16
#define NPT 4096
#define MTOT (NB*NPT)   // 65536 points

__device__ __forceinline__ float gelu_f(float x) {
    // exact tanh-approx GELU, tanh computed via exp (matches tanhf to ~1e-6)
    float u = 0.7978845608028654f * (x + 0.044715f * x * x * x);
    float a = fabsf(u);
    float e = __expf(-2.0f * a);
    float t = __fdividef(1.0f - e, 1.0f + e);
    return 0.5f * x * (1.0f + copysignf(t, u));
}

__device__ __forceinline__ uint32_t f2tf32(float x) {
    uint32_t u;
    asm("cvt.rna.tf32.f32 %0, %1;" : "=r"(u) : "f"(x));
    return u;
}

// ---------------- scratch buffers ----------------
__device__ float g_c1[NB*16*112*112];
__device__ float g_c2[NB*32*56*56];
__device__ float g_fmap[NB*4*56*56];
__device__ float g_ga[NB*4*112*112];
__device__ float g_gb[NB*8*56*56];
__device__ float g_gcs[NB*16*28*28];
__device__ float g_gd[NB*32*14*14];
__device__ float g_ge[NB*64*7*7];
__device__ float g_gvec[NB*64];
__device__ float g_gcon[NB*512];
__device__ float g_Wcat[512*512];
__device__ float g_biasC[512];
__device__ float g_embed[MTOT*48];
__device__ float g_feat[(size_t)MTOT*512];

// ---------------- templated 3x3 conv, pad 1, smem weights, gelu ----------------
template<int CIN, int STRIDE>
__global__ void conv3x3_gelu_t(const float* __restrict__ in, const float* __restrict__ w,
                               const float* __restrict__ bias, float* __restrict__ out,
                               int Hin, int Win, int Hout, int Wout) {
    __shared__ float sw[CIN * 9];
    __shared__ float sb;
    const int co = blockIdx.y;
    const int b = blockIdx.z;
    const int Cout = gridDim.y;
    for (int i = threadIdx.x; i < CIN * 9; i += blockDim.x) sw[i] = w[co * CIN * 9 + i];
    if (threadIdx.x == 0) sb = bias[co];
    __syncthreads();
    int p = blockIdx.x * blockDim.x + threadIdx.x;
    if (p >= Hout * Wout) return;
    int oy = p / Wout, ox = p % Wout;
    const float* ip = in + (size_t)b * CIN * Hin * Win;
    int iy0 = oy * STRIDE - 1, ix0 = ox * STRIDE - 1;
    float acc = sb;
    if (iy0 >= 0 && ix0 >= 0 && iy0 + 2 < Hin && ix0 + 2 < Win) {
        #pragma unroll
        for (int ci = 0; ci < CIN; ci++) {
            const float* base = ip + (size_t)ci * Hin * Win + iy0 * Win + ix0;
            const float* wp = sw + ci * 9;
            #pragma unroll
            for (int ky = 0; ky < 3; ky++)
                #pragma unroll
                for (int kx = 0; kx < 3; kx++)
                    acc += base[ky * Win + kx] * wp[ky * 3 + kx];
        }
    } else {
        #pragma unroll
        for (int ci = 0; ci < CIN; ci++) {
            const float* basec = ip + (size_t)ci * Hin * Win;
            const float* wp = sw + ci * 9;
            #pragma unroll
            for (int ky = 0; ky < 3; ky++) {
                int iy = iy0 + ky;
                #pragma unroll
                for (int kx = 0; kx < 3; kx++) {
                    int ix = ix0 + kx;
                    if (iy >= 0 && iy < Hin && ix >= 0 && ix < Win)
                        acc += basec[iy * Win + ix] * wp[ky * 3 + kx];
                }
            }
        }
    }
    out[((size_t)(b * Cout + co)) * Hout * Wout + p] = gelu_f(acc);
}

// ---------------- global pooling ----------------
__global__ void gpool_kernel() {
    int idx = blockIdx.x * blockDim.x + threadIdx.x;
    if (idx >= NB * 64) return;
    const float* p = g_ge + idx * 49;
    float s = 0.f;
    #pragma unroll
    for (int i = 0; i < 49; i++) s += p[i];
    g_gvec[idx] = s * (1.0f / 49.0f);
}

// ---------------- per-batch gc contribution ----------------
__global__ void gcon_kernel(const float* __restrict__ hw1) {
    int idx = blockIdx.x * blockDim.x + threadIdx.x;
    if (idx >= NB * 512) return;
    int b = idx >> 9, j = idx & 511;
    float acc = 0.f;
    const float* gv = g_gvec + b * 64;
    const float* hp = hw1 + j * 576 + 512;
    #pragma unroll
    for (int c = 0; c < 64; c++) acc += gv[c] * hp[c];
    g_gcon[idx] = acc;
}

// ---------------- head weight prep ----------------
__global__ void prep_head(const float* __restrict__ hw1, const float* __restrict__ hb1,
                          const float* __restrict__ lw2, const float* __restrict__ lb2) {
    int j = blockIdx.x;
    int t = threadIdx.x;
    const float* hrow = hw1 + j * 576;
    float acc = 0.f;
    for (int c = 0; c < 256; c++)
        acc += hrow[c] * lw2[c * 256 + t];
    g_Wcat[j * 512 + t] = acc;
    g_Wcat[j * 512 + 256 + t] = hrow[256 + t];
    __shared__ float s[256];
    s[t] = hrow[t] * lb2[t];
    __syncthreads();
    for (int o = 128; o > 0; o >>= 1) {
        if (t < o) s[t] += s[t + o];
        __syncthreads();
    }
    if (t == 0) g_biasC[j] = hb1[j] + s[0];
}

// ---------------- positional embedding ----------------
__global__ void embed_kernel(const float* __restrict__ points) {
    int idx = blockIdx.x * blockDim.x + threadIdx.x;
    if (idx >= MTOT * 12) return;
    int m = idx / 12, i = idx % 12;
    float f = (float)(1 << i);
    float px = points[m * 2 + 0], py = points[m * 2 + 1];
    float sx, cx, sy, cy;
    sincosf(f * px, &sx, &cx);
    sincosf(f * py, &sy, &cy);
    float* e = g_embed + m * 48 + 4 * i;
    e[0] = sx; e[1] = sy; e[2] = cx; e[3] = cy;
}

// ---------------- bilinear patch gather ----------------
__global__ void patch_kernel(const float* __restrict__ points) {
    int idx = blockIdx.x * blockDim.x + threadIdx.x;
    if (idx >= MTOT * 64) return;
    int pp = idx & 63;
    int m = idx >> 6;
    int i = pp >> 3, j = pp & 7;
    int b = m >> 12;
    float px = points[m * 2 + 0], py = points[m * 2 + 1];
    const float step = 2.0f / 55.0f;
    float gx = (px * 2.0f - 1.0f) + ((float)i - 3.5f) * step;
    float gy = (py * 2.0f - 1.0f) + ((float)j - 3.5f) * step;
    float ix = (gx + 1.0f) * 0.5f * 55.0f;
    float iy = (gy + 1.0f) * 0.5f * 55.0f;
    float x0f = floorf(ix), y0f = floorf(iy);
    int x0 = (int)x0f, y0 = (int)y0f;
    int x1 = x0 + 1, y1 = y0 + 1;
    float wx1 = ix - x0f, wx0 = 1.0f - wx1;
    float wy1 = iy - y0f, wy0 = 1.0f - wy1;
    bool vx0 = (x0 >= 0) & (x0 < 56), vx1 = (x1 >= 0) & (x1 < 56);
    bool vy0 = (y0 >= 0) & (y0 < 56), vy1 = (y1 >= 0) & (y1 < 56);
    int cx0 = min(max(x0, 0), 55), cx1 = min(max(x1, 0), 55);
    int cy0 = min(max(y0, 0), 55), cy1 = min(max(y1, 0), 55);
    float w00 = wx0 * wy0 * ((vx0 && vy0) ? 1.f : 0.f);
    float w10 = wx1 * wy0 * ((vx1 && vy0) ? 1.f : 0.f);
    float w01 = wx0 * wy1 * ((vx0 && vy1) ? 1.f : 0.f);
    float w11 = wx1 * wy1 * ((vx1 && vy1) ? 1.f : 0.f);
    int i00 = cy0 * 56 + cx0, i10 = cy0 * 56 + cx1;
    int i01 = cy1 * 56 + cx0, i11 = cy1 * 56 + cx1;
    const float* fm = g_fmap + (size_t)b * 4 * 3136;
    float* fo = g_feat + (size_t)m * 512 + 256 + pp;
    #pragma unroll
    for (int c = 0; c < 4; c++) {
        const float* base = fm + c * 3136;
        float v = w00 * base[i00] + w10 * base[i10] + w01 * base[i01] + w11 * base[i11];
        fo[c * 64] = v;
    }
}

// ---------------- out init ----------------
__global__ void init_out(float* __restrict__ out, const float* __restrict__ hb2) {
    int i = blockIdx.x * blockDim.x + threadIdx.x;
    if (i < MTOT) out[i] = hb2[0];
}

// =====================================================================================
// TF32 tensor-core GEMM, 128x128 tile, K-chunk KC, double-buffered smem,
// pair-packed (k, k+4) fragments -> 64-bit LDS fragment loads.
//   FUSED=true : out[m] += sum_j gelu(acc + bias[j] + gcon[b,j]) * hw2[j]  (atomicAdd)
//   FUSED=false: C[m,j] = gelu(acc + bias[j])                              (C = out, ldc)
// =====================================================================================
#define SMS 132   // padded row stride (uint2 units)

template<int K, int KC, bool FUSED>
__global__ __launch_bounds__(256) void gemm_tf32(
    const float* __restrict__ A, const float* __restrict__ W,
    const float* __restrict__ bias, const float* __restrict__ gcon,
    const float* __restrict__ hw2, float* __restrict__ out, int ldc) {

    constexpr int PS = KC / 2;                 // pair slots per chunk
    constexpr int NKT = K / KC;                // K chunks
    constexpr int NR = (128 * KC / 4) / 256;   // float4 loads per operand per thread
    constexpr int C4W = KC / 4;                // float4 per row per chunk
    constexpr int BUF = 2 * PS * SMS;          // uint2 per buffer (A+B)

    extern __shared__ uint2 sm[];

    const int tid = threadIdx.x;
    const int lane = tid & 31;
    const int warpId = tid >> 5;
    const int warpM = warpId & 1;        // 0..1 (64 rows each)
    const int warpN = warpId >> 1;       // 0..3 (32 cols each)
    const int tg = lane & 3;
    const int gid = lane >> 2;
    const int blockM = blockIdx.y * 128;
    const int blockN = blockIdx.x * 128;

    int lrow[NR], lc4[NR];
    #pragma unroll
    for (int r = 0; r < NR; r++) {
        int lin = r * 256 + tid;
        lrow[r] = lin / C4W;
        lc4[r] = lin % C4W;
    }
    const float* Abase = A + (size_t)blockM * K;
    const float* Wbase = W + (size_t)blockN * K;

    float4 pa[NR], pb[NR];

    auto loadg = [&](int k0) {
        #pragma unroll
        for (int r = 0; r < NR; r++) {
            pa[r] = *reinterpret_cast<const float4*>(Abase + (size_t)lrow[r] * K + k0 + lc4[r] * 4);
            pb[r] = *reinterpret_cast<const float4*>(Wbase + (size_t)lrow[r] * K + k0 + lc4[r] * 4);
        }
    };
    auto storesm = [&](int buf) {
        uint2* As = sm + buf * BUF;
        uint2* Bs = As + PS * SMS;
        #pragma unroll
        for (int r = 0; r < NR; r++) {
            int sb0 = (lc4[r] >> 1) * 4;
            int comp = lc4[r] & 1;
            uint32_t* pA0 = reinterpret_cast<uint32_t*>(&As[(sb0 + 0) * SMS + lrow[r]]);
            uint32_t* pA1 = reinterpret_cast<uint32_t*>(&As[(sb0 + 1) * SMS + lrow[r]]);
            uint32_t* pA2 = reinterpret_cast<uint32_t*>(&As[(sb0 + 2) * SMS + lrow[r]]);
            uint32_t* pA3 = reinterpret_cast<uint32_t*>(&As[(sb0 + 3) * SMS + lrow[r]]);
            pA0[comp] = f2tf32(pa[r].x); pA1[comp] = f2tf32(pa[r].y);
            pA2[comp] = f2tf32(pa[r].z); pA3[comp] = f2tf32(pa[r].w);
            uint32_t* pB0 = reinterpret_cast<uint32_t*>(&Bs[(sb0 + 0) * SMS + lrow[r]]);
            uint32_t* pB1 = reinterpret_cast<uint32_t*>(&Bs[(sb0 + 1) * SMS + lrow[r]]);
            uint32_t* pB2 = reinterpret_cast<uint32_t*>(&Bs[(sb0 + 2) * SMS + lrow[r]]);
            uint32_t* pB3 = reinterpret_cast<uint32_t*>(&Bs[(sb0 + 3) * SMS + lrow[r]]);
            pB0[comp] = f2tf32(pb[r].x); pB1[comp] = f2tf32(pb[r].y);
            pB2[comp] = f2tf32(pb[r].z); pB3[comp] = f2tf32(pb[r].w);
        }
    };

    float acc[4][4][4];
    #pragma unroll
    for (int mi = 0; mi < 4; mi++)
        #pragma unroll
        for (int ni = 0; ni < 4; ni++)
            #pragma unroll
            for (int c = 0; c < 4; c++) acc[mi][ni][c] = 0.f;

    loadg(0);
    storesm(0);
    __syncthreads();

    const int rowB = warpM * 64;
    const int colB = warpN * 32;

    #pragma unroll 1
    for (int kt = 0; kt < NKT; kt++) {
        if (kt + 1 < NKT) loadg((kt + 1) * KC);
        const uint2* As = sm + (kt & 1) * BUF;
        const uint2* Bs = As + PS * SMS;
        #pragma unroll
        for (int kk = 0; kk < KC / 8; kk++) {
            const int sb0 = kk * 4 + tg;
            uint2 a0[4], a1[4];
            #pragma unroll
            for (int mi = 0; mi < 4; mi++) {
                int r0 = rowB + mi * 16 + gid;
                a0[mi] = As[sb0 * SMS + r0];
                a1[mi] = As[sb0 * SMS + r0 + 8];
            }
            uint2 bfr[4];
            #pragma unroll
            for (int ni = 0; ni < 4; ni++) {
                int c0 = colB + ni * 8 + gid;
                bfr[ni] = Bs[sb0 * SMS + c0];
            }
            #pragma unroll
            for (int mi = 0; mi < 4; mi++)
                #pragma unroll
                for (int ni = 0; ni < 4; ni++) {
                    asm volatile(
                        "mma.sync.aligned.m16n8k8.row.col.f32.tf32.tf32.f32 "
                        "{%0,%1,%2,%3}, {%4,%5,%6,%7}, {%8,%9}, {%0,%1,%2,%3};"
                        : "+f"(acc[mi][ni][0]), "+f"(acc[mi][ni][1]),
                          "+f"(acc[mi][ni][2]), "+f"(acc[mi][ni][3])
                        : "r"(a0[mi].x), "r"(a1[mi].x), "r"(a0[mi].y), "r"(a1[mi].y),
                          "r"(bfr[ni].x), "r"(bfr[ni].y));
                }
        }
        if (kt + 1 < NKT) {
            storesm((kt + 1) & 1);
            __syncthreads();
        }
    }

    if (FUSED) {
        const int batch = blockM >> 12;
        float addc[8], w2c[8];
        #pragma unroll
        for (int ni = 0; ni < 4; ni++) {
            int c0 = blockN + colB + ni * 8 + tg * 2;
            addc[ni * 2 + 0] = bias[c0] + gcon[batch * 512 + c0];
            addc[ni * 2 + 1] = bias[c0 + 1] + gcon[batch * 512 + c0 + 1];
            w2c[ni * 2 + 0] = hw2[c0];
            w2c[ni * 2 + 1] = hw2[c0 + 1];
        }
        #pragma unroll
        for (int mi = 0; mi < 4; mi++) {
            float s0 = 0.f, s1 = 0.f;
            #pragma unroll
            for (int ni = 0; ni < 4; ni++) {
                s0 += gelu_f(acc[mi][ni][0] + addc[ni * 2 + 0]) * w2c[ni * 2 + 0];
                s0 += gelu_f(acc[mi][ni][1] + addc[ni * 2 + 1]) * w2c[ni * 2 + 1];
                s1 += gelu_f(acc[mi][ni][2] + addc[ni * 2 + 0]) * w2c[ni * 2 + 0];
                s1 += gelu_f(acc[mi][ni][3] + addc[ni * 2 + 1]) * w2c[ni * 2 + 1];
            }
            s0 += __shfl_xor_sync(0xFFFFFFFFu, s0, 1);
            s0 += __shfl_xor_sync(0xFFFFFFFFu, s0, 2);
            s1 += __shfl_xor_sync(0xFFFFFFFFu, s1, 1);
            s1 += __shfl_xor_sync(0xFFFFFFFFu, s1, 2);
            if (tg == 0) {
                int r0 = blockM + rowB + mi * 16 + gid;
                atomicAdd(out + r0, s0);
                atomicAdd(out + r0 + 8, s1);
            }
        }
    } else {
        #pragma unroll
        for (int mi = 0; mi < 4; mi++) {
            int r0 = blockM + rowB + mi * 16 + gid;
            #pragma unroll
            for (int ni = 0; ni < 4; ni++) {
                int c0 = blockN + colB + ni * 8 + tg * 2;
                float b0 = bias[c0], b1 = bias[c0 + 1];
                float2 v0 = make_float2(gelu_f(acc[mi][ni][0] + b0), gelu_f(acc[mi][ni][1] + b1));
                float2 v1 = make_float2(gelu_f(acc[mi][ni][2] + b0), gelu_f(acc[mi][ni][3] + b1));
                *reinterpret_cast<float2*>(out + (size_t)r0 * ldc + c0) = v0;
                *reinterpret_cast<float2*>(out + (size_t)(r0 + 8) * ldc + c0) = v1;
            }
        }
    }
}

// =====================================================================================
extern "C" void kernel_launch(void* const* d_in, const int* in_sizes, int n_in,
                              void* d_out, int out_size) {
    const float* points = (const float*)d_in[0];
    const float* images = (const float*)d_in[1];
    const float* pw1 = (const float*)d_in[2];  const float* pb1 = (const float*)d_in[3];
    const float* pw2 = (const float*)d_in[4];  const float* pb2 = (const float*)d_in[5];
    const float* pw3 = (const float*)d_in[6];  const float* pb3 = (const float*)d_in[7];
    const float* gw1 = (const float*)d_in[8];  const float* gb1 = (const float*)d_in[9];
    const float* gw2 = (const float*)d_in[10]; const float* gb2 = (const float*)d_in[11];
    const float* gw3 = (const float*)d_in[12]; const float* gb3 = (const float*)d_in[13];
    const float* gw4 = (const float*)d_in[14]; const float* gb4 = (const float*)d_in[15];
    const float* gw5 = (const float*)d_in[16]; const float* gb5 = (const float*)d_in[17];
    const float* lw1 = (const float*)d_in[18]; const float* lb1 = (const float*)d_in[19];
    const float* lw2 = (const float*)d_in[20]; const float* lb2 = (const float*)d_in[21];
    const float* hw1 = (const float*)d_in[22]; const float* hb1 = (const float*)d_in[23];
    const float* hw2 = (const float*)d_in[24]; const float* hb2 = (const float*)d_in[25];
    float* out = (float*)d_out;

    float *c1, *c2, *fmap, *ga, *gb_, *gcs, *gd, *ge, *Wcat, *biasC, *emb, *feat, *gcon;
    cudaGetSymbolAddress((void**)&c1, g_c1);
    cudaGetSymbolAddress((void**)&c2, g_c2);
    cudaGetSymbolAddress((void**)&fmap, g_fmap);
    cudaGetSymbolAddress((void**)&ga, g_ga);
    cudaGetSymbolAddress((void**)&gb_, g_gb);
    cudaGetSymbolAddress((void**)&gcs, g_gcs);
    cudaGetSymbolAddress((void**)&gd, g_gd);
    cudaGetSymbolAddress((void**)&ge, g_ge);
    cudaGetSymbolAddress((void**)&Wcat, g_Wcat);
    cudaGetSymbolAddress((void**)&biasC, g_biasC);
    cudaGetSymbolAddress((void**)&emb, g_embed);
    cudaGetSymbolAddress((void**)&feat, g_feat);
    cudaGetSymbolAddress((void**)&gcon, g_gcon);

    const int T = 256;
    auto blocks = [](int n) { return (n + 255) / 256; };

    // dynamic smem sizes for the tf32 GEMMs
    const int smem2 = 2 * 2 * (32 / 2) * SMS * (int)sizeof(uint2);   // 67584 B
    const int smem1 = 2 * 2 * (16 / 2) * SMS * (int)sizeof(uint2);   // 33792 B
    cudaFuncSetAttribute(gemm_tf32<512, 32, true>,
                         cudaFuncAttributeMaxDynamicSharedMemorySize, smem2);
    cudaFuncSetAttribute(gemm_tf32<48, 16, false>,
                         cudaFuncAttributeMaxDynamicSharedMemorySize, smem1);

    // ----- plane encoder -----
    conv3x3_gelu_t<3, 2><<<dim3(49, 16, NB), T>>>(images, pw1, pb1, c1, 224, 224, 112, 112);
    conv3x3_gelu_t<16, 2><<<dim3(13, 32, NB), T>>>(c1, pw2, pb2, c2, 112, 112, 56, 56);
    conv3x3_gelu_t<32, 1><<<dim3(13, 4, NB), T>>>(c2, pw3, pb3, fmap, 56, 56, 56, 56);

    // ----- global encoder -----
    conv3x3_gelu_t<3, 2><<<dim3(49, 4, NB), T>>>(images, gw1, gb1, ga, 224, 224, 112, 112);
    conv3x3_gelu_t<4, 2><<<dim3(13, 8, NB), T>>>(ga, gw2, gb2, gb_, 112, 112, 56, 56);
    conv3x3_gelu_t<8, 2><<<dim3(4, 16, NB), T>>>(gb_, gw3, gb3, gcs, 56, 56, 28, 28);
    conv3x3_gelu_t<16, 2><<<dim3(1, 32, NB), T>>>(gcs, gw4, gb4, gd, 28, 28, 14, 14);
    conv3x3_gelu_t<32, 2><<<dim3(1, 64, NB), T>>>(gd, gw5, gb5, ge, 14, 14, 7, 7);
    gpool_kernel<<<blocks(NB*64), T>>>();

    // ----- fold weights / per-batch contributions -----
    prep_head<<<512, 256>>>(hw1, hb1, lw2, lb2);
    gcon_kernel<<<blocks(NB*512), T>>>(hw1);

    // ----- point branch: embed + tf32 GEMM1 into feat[:, 0:256] -----
    embed_kernel<<<blocks(MTOT*12), T>>>(points);
    {
        dim3 grid(256 / 128, MTOT / 128);
        gemm_tf32<48, 16, false><<<grid, 256, smem1>>>(emb, lw1, lb1, nullptr, nullptr, feat, 512);
    }

    // ----- patch gather into feat[:, 256:512] -----
    patch_kernel<<<blocks(MTOT*64), T>>>(points);

    // ----- head GEMM (tf32) fused with final reduction -----
    init_out<<<blocks(MTOT), T>>>(out, hb2);
    {
        dim3 grid(512 / 128, MTOT / 128);
        gemm_tf32<512, 32, true><<<grid, 256, smem2>>>(feat, Wcat, biasC, gcon, hw2, out, 0);
    }
}

// round 14
// speedup vs baseline: 1.7780x; 1.0027x over previous
#include <cuda_runtime.h>
#include <math.h>
#include <stdint.h>

#define NB 16
#define NPT 4096
#define MTOT (NB*NPT)   // 65536 points

__device__ __forceinline__ float gelu_f(float x) {
    // exact tanh-approx GELU, tanh computed via exp (matches tanhf to ~1e-6)
    float u = 0.7978845608028654f * (x + 0.044715f * x * x * x);
    float a = fabsf(u);
    float e = __expf(-2.0f * a);
    float t = __fdividef(1.0f - e, 1.0f + e);
    return 0.5f * x * (1.0f + copysignf(t, u));
}

__device__ __forceinline__ uint32_t f2tf32(float x) {
    uint32_t u;
    asm("cvt.rna.tf32.f32 %0, %1;" : "=r"(u) : "f"(x));
    return u;
}

// ---------------- scratch buffers ----------------
__device__ float g_c1[NB*16*112*112];
__device__ float g_c2[NB*32*56*56];
__device__ float g_fmap[NB*4*56*56];
__device__ float g_ga[NB*4*112*112];
__device__ float g_gb[NB*8*56*56];
__device__ float g_gcs[NB*16*28*28];
__device__ float g_gd[NB*32*14*14];
__device__ float g_ge[NB*64*7*7];
__device__ float g_gvec[NB*64];
__device__ float g_gcon[NB*512];
__device__ float g_Wcat[512*512];
__device__ float g_biasC[512];
__device__ float g_embed[MTOT*48];
__device__ float g_feat[(size_t)MTOT*512];

// ---------------- templated 3x3 conv, pad 1, smem weights, gelu ----------------
template<int CIN, int STRIDE>
__global__ void conv3x3_gelu_t(const float* __restrict__ in, const float* __restrict__ w,
                               const float* __restrict__ bias, float* __restrict__ out,
                               int Hin, int Win, int Hout, int Wout) {
    __shared__ float sw[CIN * 9];
    __shared__ float sb;
    const int co = blockIdx.y;
    const int b = blockIdx.z;
    const int Cout = gridDim.y;
    for (int i = threadIdx.x; i < CIN * 9; i += blockDim.x) sw[i] = w[co * CIN * 9 + i];
    if (threadIdx.x == 0) sb = bias[co];
    __syncthreads();
    int p = blockIdx.x * blockDim.x + threadIdx.x;
    if (p >= Hout * Wout) return;
    int oy = p / Wout, ox = p % Wout;
    const float* ip = in + (size_t)b * CIN * Hin * Win;
    int iy0 = oy * STRIDE - 1, ix0 = ox * STRIDE - 1;
    float acc = sb;
    if (iy0 >= 0 && ix0 >= 0 && iy0 + 2 < Hin && ix0 + 2 < Win) {
        #pragma unroll
        for (int ci = 0; ci < CIN; ci++) {
            const float* base = ip + (size_t)ci * Hin * Win + iy0 * Win + ix0;
            const float* wp = sw + ci * 9;
            #pragma unroll
            for (int ky = 0; ky < 3; ky++)
                #pragma unroll
                for (int kx = 0; kx < 3; kx++)
                    acc += base[ky * Win + kx] * wp[ky * 3 + kx];
        }
    } else {
        #pragma unroll
        for (int ci = 0; ci < CIN; ci++) {
            const float* basec = ip + (size_t)ci * Hin * Win;
            const float* wp = sw + ci * 9;
            #pragma unroll
            for (int ky = 0; ky < 3; ky++) {
                int iy = iy0 + ky;
                #pragma unroll
                for (int kx = 0; kx < 3; kx++) {
                    int ix = ix0 + kx;
                    if (iy >= 0 && iy < Hin && ix >= 0 && ix < Win)
                        acc += basec[iy * Win + ix] * wp[ky * 3 + kx];
                }
            }
        }
    }
    out[((size_t)(b * Cout + co)) * Hout * Wout + p] = gelu_f(acc);
}

// ---------------- global pooling ----------------
__global__ void gpool_kernel() {
    int idx = blockIdx.x * blockDim.x + threadIdx.x;
    if (idx >= NB * 64) return;
    const float* p = g_ge + idx * 49;
    float s = 0.f;
    #pragma unroll
    for (int i = 0; i < 49; i++) s += p[i];
    g_gvec[idx] = s * (1.0f / 49.0f);
}

// ---------------- per-batch gc contribution ----------------
__global__ void gcon_kernel(const float* __restrict__ hw1) {
    int idx = blockIdx.x * blockDim.x + threadIdx.x;
    if (idx >= NB * 512) return;
    int b = idx >> 9, j = idx & 511;
    float acc = 0.f;
    const float* gv = g_gvec + b * 64;
    const float* hp = hw1 + j * 576 + 512;
    #pragma unroll
    for (int c = 0; c < 64; c++) acc += gv[c] * hp[c];
    g_gcon[idx] = acc;
}

// ---------------- head weight prep ----------------
__global__ void prep_head(const float* __restrict__ hw1, const float* __restrict__ hb1,
                          const float* __restrict__ lw2, const float* __restrict__ lb2) {
    int j = blockIdx.x;
    int t = threadIdx.x;
    const float* hrow = hw1 + j * 576;
    float acc = 0.f;
    for (int c = 0; c < 256; c++)
        acc += hrow[c] * lw2[c * 256 + t];
    g_Wcat[j * 512 + t] = acc;
    g_Wcat[j * 512 + 256 + t] = hrow[256 + t];
    __shared__ float s[256];
    s[t] = hrow[t] * lb2[t];
    __syncthreads();
    for (int o = 128; o > 0; o >>= 1) {
        if (t < o) s[t] += s[t + o];
        __syncthreads();
    }
    if (t == 0) g_biasC[j] = hb1[j] + s[0];
}

// ---------------- positional embedding ----------------
__global__ void embed_kernel(const float* __restrict__ points) {
    int idx = blockIdx.x * blockDim.x + threadIdx.x;
    if (idx >= MTOT * 12) return;
    int m = idx / 12, i = idx % 12;
    float f = (float)(1 << i);
    float px = points[m * 2 + 0], py = points[m * 2 + 1];
    float sx, cx, sy, cy;
    sincosf(f * px, &sx, &cx);
    sincosf(f * py, &sy, &cy);
    float* e = g_embed + m * 48 + 4 * i;
    e[0] = sx; e[1] = sy; e[2] = cx; e[3] = cy;
}

// ---------------- bilinear patch gather ----------------
__global__ void patch_kernel(const float* __restrict__ points) {
    int idx = blockIdx.x * blockDim.x + threadIdx.x;
    if (idx >= MTOT * 64) return;
    int pp = idx & 63;
    int m = idx >> 6;
    int i = pp >> 3, j = pp & 7;
    int b = m >> 12;
    float px = points[m * 2 + 0], py = points[m * 2 + 1];
    const float step = 2.0f / 55.0f;
    float gx = (px * 2.0f - 1.0f) + ((float)i - 3.5f) * step;
    float gy = (py * 2.0f - 1.0f) + ((float)j - 3.5f) * step;
    float ix = (gx + 1.0f) * 0.5f * 55.0f;
    float iy = (gy + 1.0f) * 0.5f * 55.0f;
    float x0f = floorf(ix), y0f = floorf(iy);
    int x0 = (int)x0f, y0 = (int)y0f;
    int x1 = x0 + 1, y1 = y0 + 1;
    float wx1 = ix - x0f, wx0 = 1.0f - wx1;
    float wy1 = iy - y0f, wy0 = 1.0f - wy1;
    bool vx0 = (x0 >= 0) & (x0 < 56), vx1 = (x1 >= 0) & (x1 < 56);
    bool vy0 = (y0 >= 0) & (y0 < 56), vy1 = (y1 >= 0) & (y1 < 56);
    int cx0 = min(max(x0, 0), 55), cx1 = min(max(x1, 0), 55);
    int cy0 = min(max(y0, 0), 55), cy1 = min(max(y1, 0), 55);
    float w00 = wx0 * wy0 * ((vx0 && vy0) ? 1.f : 0.f);
    float w10 = wx1 * wy0 * ((vx1 && vy0) ? 1.f : 0.f);
    float w01 = wx0 * wy1 * ((vx0 && vy1) ? 1.f : 0.f);
    float w11 = wx1 * wy1 * ((vx1 && vy1) ? 1.f : 0.f);
    int i00 = cy0 * 56 + cx0, i10 = cy0 * 56 + cx1;
    int i01 = cy1 * 56 + cx0, i11 = cy1 * 56 + cx1;
    const float* fm = g_fmap + (size_t)b * 4 * 3136;
    float* fo = g_feat + (size_t)m * 512 + 256 + pp;
    #pragma unroll
    for (int c = 0; c < 4; c++) {
        const float* base = fm + c * 3136;
        float v = w00 * base[i00] + w10 * base[i10] + w01 * base[i01] + w11 * base[i11];
        fo[c * 64] = v;
    }
}

// ---------------- out init ----------------
__global__ void init_out(float* __restrict__ out, const float* __restrict__ hb2) {
    int i = blockIdx.x * blockDim.x + threadIdx.x;
    if (i < MTOT) out[i] = hb2[0];
}

// =====================================================================================
// TF32 tensor-core GEMM, 128x128 tile, K-chunk KC, double-buffered smem,
// pair-packed (k, k+4) fragments -> 64-bit LDS fragment loads.
//   FUSED=true : out[m] += sum_j gelu(acc + bias[j] + gcon[b,j]) * hw2[j]  (atomicAdd)
//   FUSED=false: C[m,j] = gelu(acc + bias[j])                              (C = out, ldc)
// =====================================================================================
#define SMS 132   // padded row stride (uint2 units)

template<int K, int KC, bool FUSED>
__global__ __launch_bounds__(256) void gemm_tf32(
    const float* __restrict__ A, const float* __restrict__ W,
    const float* __restrict__ bias, const float* __restrict__ gcon,
    const float* __restrict__ hw2, float* __restrict__ out, int ldc) {

    constexpr int PS = KC / 2;                 // pair slots per chunk
    constexpr int NKT = K / KC;                // K chunks
    constexpr int NR = (128 * KC / 4) / 256;   // float4 loads per operand per thread
    constexpr int C4W = KC / 4;                // float4 per row per chunk
    constexpr int BUF = 2 * PS * SMS;          // uint2 per buffer (A+B)

    extern __shared__ uint2 sm[];

    const int tid = threadIdx.x;
    const int lane = tid & 31;
    const int warpId = tid >> 5;
    const int warpM = warpId & 1;        // 0..1 (64 rows each)
    const int warpN = warpId >> 1;       // 0..3 (32 cols each)
    const int tg = lane & 3;
    const int gid = lane >> 2;
    const int blockM = blockIdx.y * 128;
    const int blockN = blockIdx.x * 128;

    int lrow[NR], lc4[NR];
    #pragma unroll
    for (int r = 0; r < NR; r++) {
        int lin = r * 256 + tid;
        lrow[r] = lin / C4W;
        lc4[r] = lin % C4W;
    }
    const float* Abase = A + (size_t)blockM * K;
    const float* Wbase = W + (size_t)blockN * K;

    float4 pa[NR], pb[NR];

    auto loadg = [&](int k0) {
        #pragma unroll
        for (int r = 0; r < NR; r++) {
            pa[r] = *reinterpret_cast<const float4*>(Abase + (size_t)lrow[r] * K + k0 + lc4[r] * 4);
            pb[r] = *reinterpret_cast<const float4*>(Wbase + (size_t)lrow[r] * K + k0 + lc4[r] * 4);
        }
    };
    auto storesm = [&](int buf) {
        uint2* As = sm + buf * BUF;
        uint2* Bs = As + PS * SMS;
        #pragma unroll
        for (int r = 0; r < NR; r++) {
            int sb0 = (lc4[r] >> 1) * 4;
            int comp = lc4[r] & 1;
            uint32_t* pA0 = reinterpret_cast<uint32_t*>(&As[(sb0 + 0) * SMS + lrow[r]]);
            uint32_t* pA1 = reinterpret_cast<uint32_t*>(&As[(sb0 + 1) * SMS + lrow[r]]);
            uint32_t* pA2 = reinterpret_cast<uint32_t*>(&As[(sb0 + 2) * SMS + lrow[r]]);
            uint32_t* pA3 = reinterpret_cast<uint32_t*>(&As[(sb0 + 3) * SMS + lrow[r]]);
            pA0[comp] = f2tf32(pa[r].x); pA1[comp] = f2tf32(pa[r].y);
            pA2[comp] = f2tf32(pa[r].z); pA3[comp] = f2tf32(pa[r].w);
            uint32_t* pB0 = reinterpret_cast<uint32_t*>(&Bs[(sb0 + 0) * SMS + lrow[r]]);
            uint32_t* pB1 = reinterpret_cast<uint32_t*>(&Bs[(sb0 + 1) * SMS + lrow[r]]);
            uint32_t* pB2 = reinterpret_cast<uint32_t*>(&Bs[(sb0 + 2) * SMS + lrow[r]]);
            uint32_t* pB3 = reinterpret_cast<uint32_t*>(&Bs[(sb0 + 3) * SMS + lrow[r]]);
            pB0[comp] = f2tf32(pb[r].x); pB1[comp] = f2tf32(pb[r].y);
            pB2[comp] = f2tf32(pb[r].z); pB3[comp] = f2tf32(pb[r].w);
        }
    };

    float acc[4][4][4];
    #pragma unroll
    for (int mi = 0; mi < 4; mi++)
        #pragma unroll
        for (int ni = 0; ni < 4; ni++)
            #pragma unroll
            for (int c = 0; c < 4; c++) acc[mi][ni][c] = 0.f;

    loadg(0);
    storesm(0);
    __syncthreads();

    const int rowB = warpM * 64;
    const int colB = warpN * 32;

    #pragma unroll 1
    for (int kt = 0; kt < NKT; kt++) {
        if (kt + 1 < NKT) loadg((kt + 1) * KC);
        const uint2* As = sm + (kt & 1) * BUF;
        const uint2* Bs = As + PS * SMS;
        #pragma unroll
        for (int kk = 0; kk < KC / 8; kk++) {
            const int sb0 = kk * 4 + tg;
            uint2 a0[4], a1[4];
            #pragma unroll
            for (int mi = 0; mi < 4; mi++) {
                int r0 = rowB + mi * 16 + gid;
                a0[mi] = As[sb0 * SMS + r0];
                a1[mi] = As[sb0 * SMS + r0 + 8];
            }
            uint2 bfr[4];
            #pragma unroll
            for (int ni = 0; ni < 4; ni++) {
                int c0 = colB + ni * 8 + gid;
                bfr[ni] = Bs[sb0 * SMS + c0];
            }
            #pragma unroll
            for (int mi = 0; mi < 4; mi++)
                #pragma unroll
                for (int ni = 0; ni < 4; ni++) {
                    asm volatile(
                        "mma.sync.aligned.m16n8k8.row.col.f32.tf32.tf32.f32 "
                        "{%0,%1,%2,%3}, {%4,%5,%6,%7}, {%8,%9}, {%0,%1,%2,%3};"
                        : "+f"(acc[mi][ni][0]), "+f"(acc[mi][ni][1]),
                          "+f"(acc[mi][ni][2]), "+f"(acc[mi][ni][3])
                        : "r"(a0[mi].x), "r"(a1[mi].x), "r"(a0[mi].y), "r"(a1[mi].y),
                          "r"(bfr[ni].x), "r"(bfr[ni].y));
                }
        }
        if (kt + 1 < NKT) {
            storesm((kt + 1) & 1);
            __syncthreads();
        }
    }

    if (FUSED) {
        const int batch = blockM >> 12;
        float addc[8], w2c[8];
        #pragma unroll
        for (int ni = 0; ni < 4; ni++) {
            int c0 = blockN + colB + ni * 8 + tg * 2;
            addc[ni * 2 + 0] = bias[c0] + gcon[batch * 512 + c0];
            addc[ni * 2 + 1] = bias[c0 + 1] + gcon[batch * 512 + c0 + 1];
            w2c[ni * 2 + 0] = hw2[c0];
            w2c[ni * 2 + 1] = hw2[c0 + 1];
        }
        #pragma unroll
        for (int mi = 0; mi < 4; mi++) {
            float s0 = 0.f, s1 = 0.f;
            #pragma unroll
            for (int ni = 0; ni < 4; ni++) {
                s0 += gelu_f(acc[mi][ni][0] + addc[ni * 2 + 0]) * w2c[ni * 2 + 0];
                s0 += gelu_f(acc[mi][ni][1] + addc[ni * 2 + 1]) * w2c[ni * 2 + 1];
                s1 += gelu_f(acc[mi][ni][2] + addc[ni * 2 + 0]) * w2c[ni * 2 + 0];
                s1 += gelu_f(acc[mi][ni][3] + addc[ni * 2 + 1]) * w2c[ni * 2 + 1];
            }
            s0 += __shfl_xor_sync(0xFFFFFFFFu, s0, 1);
            s0 += __shfl_xor_sync(0xFFFFFFFFu, s0, 2);
            s1 += __shfl_xor_sync(0xFFFFFFFFu, s1, 1);
            s1 += __shfl_xor_sync(0xFFFFFFFFu, s1, 2);
            if (tg == 0) {
                int r0 = blockM + rowB + mi * 16 + gid;
                atomicAdd(out + r0, s0);
                atomicAdd(out + r0 + 8, s1);
            }
        }
    } else {
        #pragma unroll
        for (int mi = 0; mi < 4; mi++) {
            int r0 = blockM + rowB + mi * 16 + gid;
            #pragma unroll
            for (int ni = 0; ni < 4; ni++) {
                int c0 = blockN + colB + ni * 8 + tg * 2;
                float b0 = bias[c0], b1 = bias[c0 + 1];
                float2 v0 = make_float2(gelu_f(acc[mi][ni][0] + b0), gelu_f(acc[mi][ni][1] + b1));
                float2 v1 = make_float2(gelu_f(acc[mi][ni][2] + b0), gelu_f(acc[mi][ni][3] + b1));
                *reinterpret_cast<float2*>(out + (size_t)r0 * ldc + c0) = v0;
                *reinterpret_cast<float2*>(out + (size_t)(r0 + 8) * ldc + c0) = v1;
            }
        }
    }
}

// =====================================================================================
extern "C" void kernel_launch(void* const* d_in, const int* in_sizes, int n_in,
                              void* d_out, int out_size) {
    const float* points = (const float*)d_in[0];
    const float* images = (const float*)d_in[1];
    const float* pw1 = (const float*)d_in[2];  const float* pb1 = (const float*)d_in[3];
    const float* pw2 = (const float*)d_in[4];  const float* pb2 = (const float*)d_in[5];
    const float* pw3 = (const float*)d_in[6];  const float* pb3 = (const float*)d_in[7];
    const float* gw1 = (const float*)d_in[8];  const float* gb1 = (const float*)d_in[9];
    const float* gw2 = (const float*)d_in[10]; const float* gb2 = (const float*)d_in[11];
    const float* gw3 = (const float*)d_in[12]; const float* gb3 = (const float*)d_in[13];
    const float* gw4 = (const float*)d_in[14]; const float* gb4 = (const float*)d_in[15];
    const float* gw5 = (const float*)d_in[16]; const float* gb5 = (const float*)d_in[17];
    const float* lw1 = (const float*)d_in[18]; const float* lb1 = (const float*)d_in[19];
    const float* lw2 = (const float*)d_in[20]; const float* lb2 = (const float*)d_in[21];
    const float* hw1 = (const float*)d_in[22]; const float* hb1 = (const float*)d_in[23];
    const float* hw2 = (const float*)d_in[24]; const float* hb2 = (const float*)d_in[25];
    float* out = (float*)d_out;

    float *c1, *c2, *fmap, *ga, *gb_, *gcs, *gd, *ge, *Wcat, *biasC, *emb, *feat, *gcon;
    cudaGetSymbolAddress((void**)&c1, g_c1);
    cudaGetSymbolAddress((void**)&c2, g_c2);
    cudaGetSymbolAddress((void**)&fmap, g_fmap);
    cudaGetSymbolAddress((void**)&ga, g_ga);
    cudaGetSymbolAddress((void**)&gb_, g_gb);
    cudaGetSymbolAddress((void**)&gcs, g_gcs);
    cudaGetSymbolAddress((void**)&gd, g_gd);
    cudaGetSymbolAddress((void**)&ge, g_ge);
    cudaGetSymbolAddress((void**)&Wcat, g_Wcat);
    cudaGetSymbolAddress((void**)&biasC, g_biasC);
    cudaGetSymbolAddress((void**)&emb, g_embed);
    cudaGetSymbolAddress((void**)&feat, g_feat);
    cudaGetSymbolAddress((void**)&gcon, g_gcon);

    const int T = 256;
    auto blocks = [](int n) { return (n + 255) / 256; };

    // dynamic smem sizes for the tf32 GEMMs
    const int smem2 = 2 * 2 * (32 / 2) * SMS * (int)sizeof(uint2);   // 67584 B
    const int smem1 = 2 * 2 * (16 / 2) * SMS * (int)sizeof(uint2);   // 33792 B
    cudaFuncSetAttribute(gemm_tf32<512, 32, true>,
                         cudaFuncAttributeMaxDynamicSharedMemorySize, smem2);
    cudaFuncSetAttribute(gemm_tf32<48, 16, false>,
                         cudaFuncAttributeMaxDynamicSharedMemorySize, smem1);

    // ----- plane encoder -----
    conv3x3_gelu_t<3, 2><<<dim3(49, 16, NB), T>>>(images, pw1, pb1, c1, 224, 224, 112, 112);
    conv3x3_gelu_t<16, 2><<<dim3(13, 32, NB), T>>>(c1, pw2, pb2, c2, 112, 112, 56, 56);
    conv3x3_gelu_t<32, 1><<<dim3(13, 4, NB), T>>>(c2, pw3, pb3, fmap, 56, 56, 56, 56);

    // ----- global encoder -----
    conv3x3_gelu_t<3, 2><<<dim3(49, 4, NB), T>>>(images, gw1, gb1, ga, 224, 224, 112, 112);
    conv3x3_gelu_t<4, 2><<<dim3(13, 8, NB), T>>>(ga, gw2, gb2, gb_, 112, 112, 56, 56);
    conv3x3_gelu_t<8, 2><<<dim3(4, 16, NB), T>>>(gb_, gw3, gb3, gcs, 56, 56, 28, 28);
    conv3x3_gelu_t<16, 2><<<dim3(1, 32, NB), T>>>(gcs, gw4, gb4, gd, 28, 28, 14, 14);
    conv3x3_gelu_t<32, 2><<<dim3(1, 64, NB), T>>>(gd, gw5, gb5, ge, 14, 14, 7, 7);
    gpool_kernel<<<blocks(NB*64), T>>>();

    // ----- fold weights / per-batch contributions -----
    prep_head<<<512, 256>>>(hw1, hb1, lw2, lb2);
    gcon_kernel<<<blocks(NB*512), T>>>(hw1);

    // ----- point branch: embed + tf32 GEMM1 into feat[:, 0:256] -----
    embed_kernel<<<blocks(MTOT*12), T>>>(points);
    {
        dim3 grid(256 / 128, MTOT / 128);
        gemm_tf32<48, 16, false><<<grid, 256, smem1>>>(emb, lw1, lb1, nullptr, nullptr, feat, 512);
    }

    // ----- patch gather into feat[:, 256:512] -----
    patch_kernel<<<blocks(MTOT*64), T>>>(points);

    // ----- head GEMM (tf32) fused with final reduction -----
    init_out<<<blocks(MTOT), T>>>(out, hb2);
    {
        dim3 grid(512 / 128, MTOT / 128);
        gemm_tf32<512, 32, true><<<grid, 256, smem2>>>(feat, Wcat, biasC, gcon, hw2, out, 0);
    }
}